// round 1
// baseline (speedup 1.0000x reference)
#include <cuda_runtime.h>
#include <math.h>

#define DIM 2048
#define NH 16
#define NKV 4
#define HD 128
#define BB 4
#define SS 2048
#define KVD 512        // NKV*HD
#define QKVD 3072      // DIM + 2*KVD
#define MROWS (BB*SS)  // 8192

// ---------------- scratch (no allocations allowed) ----------------
__device__ float g_qkv[(size_t)BB*SS*QKVD];   // 100.7 MB
__device__ float g_q[(size_t)BB*NH*SS*HD];    // 67 MB
__device__ float g_k[(size_t)BB*NKV*SS*HD];   // 16.8 MB
__device__ float g_v[(size_t)BB*NKV*SS*HD];   // 16.8 MB
__device__ float g_y[(size_t)BB*SS*DIM];      // 67 MB

// =====================================================================
// SGEMM: C[m, coloff+n] = sum_k A[m,k] * W[n,k]   (A row-major MxK,
// W row-major NxK, C row-major with leading dim ldc). 128x128x16 tiles,
// 256 threads, 8x8 microtile with strided (ty+16i, tx+16j) mapping.
// =====================================================================
__global__ __launch_bounds__(256, 2)
void gemm_nt(const float* __restrict__ A, const float* __restrict__ W,
             float* __restrict__ C, int M, int N, int K, int ldc, int coloff)
{
    __shared__ float As[128 * 16];
    __shared__ float Bs[16 * 132];   // transposed W tile, padded

    const int tid = threadIdx.x;
    const int tx = tid & 15;
    const int ty = tid >> 4;
    const int m0 = blockIdx.y * 128;
    const int n0 = blockIdx.x * 128;

    float acc[8][8];
#pragma unroll
    for (int i = 0; i < 8; i++)
#pragma unroll
        for (int j = 0; j < 8; j++) acc[i][j] = 0.f;

    for (int k0 = 0; k0 < K; k0 += 16) {
        // load A tile 128x16 (512 float4, 2 per thread)
#pragma unroll
        for (int r = 0; r < 2; r++) {
            int f4  = tid + 256 * r;
            int row = f4 >> 2;
            int kc  = (f4 & 3) * 4;
            float4 va = *(const float4*)(A + (size_t)(m0 + row) * K + k0 + kc);
            *(float4*)(As + row * 16 + kc) = va;
        }
        // load W tile 128x16, store transposed -> Bs[k][n]
#pragma unroll
        for (int r = 0; r < 2; r++) {
            int f4  = tid + 256 * r;
            int row = f4 >> 2;
            int kc  = (f4 & 3) * 4;
            float4 vb = *(const float4*)(W + (size_t)(n0 + row) * K + k0 + kc);
            Bs[(kc + 0) * 132 + row] = vb.x;
            Bs[(kc + 1) * 132 + row] = vb.y;
            Bs[(kc + 2) * 132 + row] = vb.z;
            Bs[(kc + 3) * 132 + row] = vb.w;
        }
        __syncthreads();

#pragma unroll
        for (int k = 0; k < 16; k++) {
            float a[8], b[8];
#pragma unroll
            for (int i = 0; i < 8; i++) a[i] = As[(ty + 16 * i) * 16 + k];
#pragma unroll
            for (int j = 0; j < 8; j++) b[j] = Bs[k * 132 + tx + 16 * j];
#pragma unroll
            for (int i = 0; i < 8; i++)
#pragma unroll
                for (int j = 0; j < 8; j++) acc[i][j] += a[i] * b[j];
        }
        __syncthreads();
    }

#pragma unroll
    for (int i = 0; i < 8; i++) {
        int row = m0 + ty + 16 * i;
#pragma unroll
        for (int j = 0; j < 8; j++) {
            C[(size_t)row * ldc + coloff + n0 + tx + 16 * j] = acc[i][j];
        }
    }
}

// =====================================================================
// RMS-norm + RoPE + gain + reshape into [B, heads, S, hd] layouts.
// grid: x = B*S, y = NH + 2*NKV (q heads | k heads | v copy). block 128.
// =====================================================================
__global__ void norm_rope(const float* __restrict__ qkv,
                          const float* __restrict__ q_gain,
                          float* __restrict__ q, float* __restrict__ k,
                          float* __restrict__ v)
{
    const int bs   = blockIdx.x;
    const int head = blockIdx.y;
    const int b = bs / SS, s = bs % SS;
    const int d = threadIdx.x;

    if (head >= NH + NKV) {            // V: pure copy/reshape
        int kv = head - NH - NKV;
        float val = qkv[(size_t)bs * QKVD + DIM + KVD + kv * HD + d];
        v[((size_t)(b * NKV + kv) * SS + s) * HD + d] = val;
        return;
    }
    const bool isq = (head < NH);
    const float* row = qkv + (size_t)bs * QKVD +
                       (isq ? head * HD : DIM + (head - NH) * HD);
    float val = row[d];

    __shared__ float red[4];
    __shared__ float xs[HD];
    float sq = val * val;
#pragma unroll
    for (int o = 16; o > 0; o >>= 1) sq += __shfl_xor_sync(0xffffffffu, sq, o);
    if ((d & 31) == 0) red[d >> 5] = sq;
    __syncthreads();
    float ms = (red[0] + red[1] + red[2] + red[3]) * (1.0f / HD);
    float xn = val * rsqrtf(ms + 1.1920929e-07f);
    xs[d] = xn;
    __syncthreads();

    float outv;
    if (d < 64) {
        int f = d & 31;
        double inv = pow(10000.0, -(double)f / 32.0);
        double ang = (double)s * inv;
        double sd, cd;
        sincos(ang, &sd, &cd);
        float c = (float)cd, sn = (float)sd;
        float x1 = xs[f], x2 = xs[f + 32];
        outv = (d < 32) ? (x1 * c + x2 * sn) : (-x1 * sn + x2 * c);
    } else {
        outv = xn;
    }

    if (isq) {
        outv *= q_gain[head];
        q[((size_t)(b * NH + head) * SS + s) * HD + d] = outv;
    } else {
        int kv = head - NH;
        k[((size_t)(b * NKV + kv) * SS + s) * HD + d] = outv;
    }
}

// =====================================================================
// Causal flash attention, fp32. grid (S/64, NH, B), 256 threads.
// 64-row Q tile; loop kv tiles 0..qt with online softmax.
// =====================================================================
#define ABM 64
#define ABN 64
#define ATTN_SMEM_FLOATS (64*128 + 128*64 + 64*128 + 64*65 + 3*64)

__global__ __launch_bounds__(256, 1)
void attn_kernel(const float* __restrict__ q, const float* __restrict__ k,
                 const float* __restrict__ v, float* __restrict__ y)
{
    extern __shared__ float sm[];
    float* Qs   = sm;                    // [64][128]
    float* Kst  = Qs  + 64 * 128;        // [128][64] transposed
    float* Vs   = Kst + 128 * 64;        // [64][128]
    float* Ps   = Vs  + 64 * 128;        // [64][65]
    float* m_s  = Ps  + 64 * 65;
    float* l_s  = m_s + 64;
    float* al_s = l_s + 64;

    const int qt = blockIdx.x, h = blockIdx.y, b = blockIdx.z;
    const int kvh = h >> 2;              // GQA: 4 q-heads per kv-head
    const int tid = threadIdx.x;
    const int tx = tid & 15, ty = tid >> 4;
    const float scale = 0.08838834764831845f;  // 1/sqrt(128)

    const float* qbase = q + ((size_t)(b * NH + h) * SS + qt * ABM) * HD;
    const float* kbase = k + ((size_t)(b * NKV + kvh) * SS) * HD;
    const float* vbase = v + ((size_t)(b * NKV + kvh) * SS) * HD;

    // load Q tile (2048 float4)
#pragma unroll
    for (int r = 0; r < 8; r++) {
        int f4 = tid + 256 * r;
        int row = f4 >> 5, dc = (f4 & 31) * 4;
        *(float4*)(Qs + row * HD + dc) = *(const float4*)(qbase + row * HD + dc);
    }
    if (tid < 64) { m_s[tid] = -1e30f; l_s[tid] = 0.f; }

    float acc[32];
#pragma unroll
    for (int c = 0; c < 32; c++) acc[c] = 0.f;
    const int prow = tid >> 2;
    const int pcol = (tid & 3) * 32;
    __syncthreads();

    for (int kvt = 0; kvt <= qt; kvt++) {
        // load K (transposed into Kst) and V
#pragma unroll
        for (int r = 0; r < 8; r++) {
            int f4 = tid * 8 + r;
            int row = f4 >> 5, dc = (f4 & 31) * 4;
            float4 k4 = *(const float4*)(kbase + (size_t)(kvt * ABN + row) * HD + dc);
            Kst[(dc + 0) * 64 + row] = k4.x;
            Kst[(dc + 1) * 64 + row] = k4.y;
            Kst[(dc + 2) * 64 + row] = k4.z;
            Kst[(dc + 3) * 64 + row] = k4.w;
            float4 v4 = *(const float4*)(vbase + (size_t)(kvt * ABN + row) * HD + dc);
            *(float4*)(Vs + row * HD + dc) = v4;
        }
        __syncthreads();

        // S = Q K^T (4x4 microtile)
        float sacc[4][4];
#pragma unroll
        for (int i = 0; i < 4; i++)
#pragma unroll
            for (int j = 0; j < 4; j++) sacc[i][j] = 0.f;

        for (int kk = 0; kk < HD; kk++) {
            float a[4], bb[4];
#pragma unroll
            for (int i = 0; i < 4; i++) a[i] = Qs[(ty + 16 * i) * HD + kk];
#pragma unroll
            for (int j = 0; j < 4; j++) bb[j] = Kst[kk * 64 + tx + 16 * j];
#pragma unroll
            for (int i = 0; i < 4; i++)
#pragma unroll
                for (int j = 0; j < 4; j++) sacc[i][j] += a[i] * bb[j];
        }

        const bool diag = (kvt == qt);
#pragma unroll
        for (int i = 0; i < 4; i++)
#pragma unroll
            for (int j = 0; j < 4; j++) {
                float sv = sacc[i][j] * scale;
                if (diag && (tx + 16 * j > ty + 16 * i)) sv = -1e30f;
                sacc[i][j] = sv;
            }

        // online softmax (each row owned by 16 threads with same ty)
#pragma unroll
        for (int i = 0; i < 4; i++) {
            int r = ty + 16 * i;
            float rm = fmaxf(fmaxf(sacc[i][0], sacc[i][1]),
                             fmaxf(sacc[i][2], sacc[i][3]));
#pragma unroll
            for (int o = 1; o < 16; o <<= 1)
                rm = fmaxf(rm, __shfl_xor_sync(0xffffffffu, rm, o));
            float mold = m_s[r];
            float mnew = fmaxf(mold, rm);
            float rs = 0.f;
#pragma unroll
            for (int j = 0; j < 4; j++) {
                float p = expf(sacc[i][j] - mnew);
                Ps[r * 65 + tx + 16 * j] = p;
                rs += p;
            }
#pragma unroll
            for (int o = 1; o < 16; o <<= 1)
                rs += __shfl_xor_sync(0xffffffffu, rs, o);
            if (tx == 0) {
                float alpha = expf(mold - mnew);
                al_s[r] = alpha;
                m_s[r]  = mnew;
                l_s[r]  = l_s[r] * alpha + rs;
            }
        }
        __syncthreads();

        // O += P V  (thread owns 1 row x 32 cols)
        float al = al_s[prow];
#pragma unroll
        for (int c = 0; c < 32; c++) acc[c] *= al;
        for (int j = 0; j < 64; j++) {
            float p = Ps[prow * 65 + j];
            const float* vr = Vs + j * HD + pcol;
#pragma unroll
            for (int c = 0; c < 32; c += 4) {
                float4 v4 = *(const float4*)(vr + c);
                acc[c]     += p * v4.x;
                acc[c + 1] += p * v4.y;
                acc[c + 2] += p * v4.z;
                acc[c + 3] += p * v4.w;
            }
        }
        __syncthreads();
    }

    // normalize and write y[b][s][h*128 + c]
    float linv = 1.0f / l_s[prow];
    float* yrow = y + ((size_t)b * SS + qt * ABM + prow) * DIM + h * HD + pcol;
#pragma unroll
    for (int c = 0; c < 32; c += 4) {
        float4 o4 = make_float4(acc[c] * linv, acc[c + 1] * linv,
                                acc[c + 2] * linv, acc[c + 3] * linv);
        *(float4*)(yrow + c) = o4;
    }
}

// =====================================================================
// host
// =====================================================================
extern "C" void kernel_launch(void* const* d_in, const int* in_sizes, int n_in,
                              void* d_out, int out_size)
{
    const float* x     = (const float*)d_in[0];
    const float* Wq    = (const float*)d_in[1];
    const float* Wk    = (const float*)d_in[2];
    const float* Wv    = (const float*)d_in[3];
    const float* Wproj = (const float*)d_in[4];
    const float* qg    = (const float*)d_in[5];
    float* out = (float*)d_out;

    float *qkv, *q, *k, *v, *y;
    cudaGetSymbolAddress((void**)&qkv, g_qkv);
    cudaGetSymbolAddress((void**)&q,   g_q);
    cudaGetSymbolAddress((void**)&k,   g_k);
    cudaGetSymbolAddress((void**)&v,   g_v);
    cudaGetSymbolAddress((void**)&y,   g_y);

    cudaFuncSetAttribute(attn_kernel,
                         cudaFuncAttributeMaxDynamicSharedMemorySize,
                         ATTN_SMEM_FLOATS * sizeof(float));

    // 1) QKV projections into g_qkv (ldc = 3072)
    gemm_nt<<<dim3(DIM / 128, MROWS / 128), 256>>>(x, Wq, qkv, MROWS, DIM, DIM, QKVD, 0);
    gemm_nt<<<dim3(KVD / 128, MROWS / 128), 256>>>(x, Wk, qkv, MROWS, KVD, DIM, QKVD, DIM);
    gemm_nt<<<dim3(KVD / 128, MROWS / 128), 256>>>(x, Wv, qkv, MROWS, KVD, DIM, QKVD, DIM + KVD);

    // 2) RMS-norm + RoPE + gain + reshape
    norm_rope<<<dim3(BB * SS, NH + 2 * NKV), 128>>>(qkv, qg, q, k, v);

    // 3) causal flash attention -> g_y
    attn_kernel<<<dim3(SS / ABM, NH, BB), 256,
                  ATTN_SMEM_FLOATS * sizeof(float)>>>(q, k, v, y);

    // 4) output projection -> d_out
    gemm_nt<<<dim3(DIM / 128, MROWS / 128), 256>>>(y, Wproj, out, MROWS, DIM, DIM, DIM, 0);
}

// round 2
// speedup vs baseline: 1.0012x; 1.0012x over previous
#include <cuda_runtime.h>
#include <math.h>

#define DIM 2048
#define NH 16
#define NKV 4
#define HD 128
#define BB 4
#define SS 2048
#define KVD 512        // NKV*HD
#define QKVD 3072      // DIM + 2*KVD
#define MROWS (BB*SS)  // 8192

// ---------------- scratch (no allocations allowed) ----------------
__device__ float g_qkv[(size_t)BB*SS*QKVD];   // 100.7 MB
__device__ float g_q[(size_t)BB*NH*SS*HD];    // 67 MB
__device__ float g_k[(size_t)BB*NKV*SS*HD];   // 16.8 MB
__device__ float g_v[(size_t)BB*NKV*SS*HD];   // 16.8 MB
__device__ float g_y[(size_t)BB*SS*DIM];      // 67 MB

// =====================================================================
// SGEMM: C[m, coloff+n] = sum_k A[m,k] * W[n,k]   (A row-major MxK,
// W row-major NxK, C row-major with leading dim ldc). 128x128x16 tiles,
// 256 threads, 8x8 microtile with strided (ty+16i, tx+16j) mapping.
// =====================================================================
__global__ __launch_bounds__(256, 2)
void gemm_nt(const float* __restrict__ A, const float* __restrict__ W,
             float* __restrict__ C, int M, int N, int K, int ldc, int coloff)
{
    __shared__ float As[128 * 16];
    __shared__ float Bs[16 * 132];   // transposed W tile, padded

    const int tid = threadIdx.x;
    const int tx = tid & 15;
    const int ty = tid >> 4;
    const int m0 = blockIdx.y * 128;
    const int n0 = blockIdx.x * 128;

    float acc[8][8];
#pragma unroll
    for (int i = 0; i < 8; i++)
#pragma unroll
        for (int j = 0; j < 8; j++) acc[i][j] = 0.f;

    for (int k0 = 0; k0 < K; k0 += 16) {
        // load A tile 128x16 (512 float4, 2 per thread)
#pragma unroll
        for (int r = 0; r < 2; r++) {
            int f4  = tid + 256 * r;
            int row = f4 >> 2;
            int kc  = (f4 & 3) * 4;
            float4 va = *(const float4*)(A + (size_t)(m0 + row) * K + k0 + kc);
            *(float4*)(As + row * 16 + kc) = va;
        }
        // load W tile 128x16, store transposed -> Bs[k][n]
#pragma unroll
        for (int r = 0; r < 2; r++) {
            int f4  = tid + 256 * r;
            int row = f4 >> 2;
            int kc  = (f4 & 3) * 4;
            float4 vb = *(const float4*)(W + (size_t)(n0 + row) * K + k0 + kc);
            Bs[(kc + 0) * 132 + row] = vb.x;
            Bs[(kc + 1) * 132 + row] = vb.y;
            Bs[(kc + 2) * 132 + row] = vb.z;
            Bs[(kc + 3) * 132 + row] = vb.w;
        }
        __syncthreads();

#pragma unroll
        for (int k = 0; k < 16; k++) {
            float a[8], b[8];
#pragma unroll
            for (int i = 0; i < 8; i++) a[i] = As[(ty + 16 * i) * 16 + k];
#pragma unroll
            for (int j = 0; j < 8; j++) b[j] = Bs[k * 132 + tx + 16 * j];
#pragma unroll
            for (int i = 0; i < 8; i++)
#pragma unroll
                for (int j = 0; j < 8; j++) acc[i][j] += a[i] * b[j];
        }
        __syncthreads();
    }

#pragma unroll
    for (int i = 0; i < 8; i++) {
        int row = m0 + ty + 16 * i;
#pragma unroll
        for (int j = 0; j < 8; j++) {
            C[(size_t)row * ldc + coloff + n0 + tx + 16 * j] = acc[i][j];
        }
    }
}

// =====================================================================
// RMS-norm + RoPE + gain + reshape into [B, heads, S, hd] layouts.
// grid: x = B*S, y = NH + 2*NKV (q heads | k heads | v copy). block 128.
// =====================================================================
__global__ void norm_rope(const float* __restrict__ qkv,
                          const float* __restrict__ q_gain,
                          float* __restrict__ q, float* __restrict__ k,
                          float* __restrict__ v)
{
    const int bs   = blockIdx.x;
    const int head = blockIdx.y;
    const int b = bs / SS, s = bs % SS;
    const int d = threadIdx.x;

    if (head >= NH + NKV) {            // V: pure copy/reshape
        int kv = head - NH - NKV;
        float val = qkv[(size_t)bs * QKVD + DIM + KVD + kv * HD + d];
        v[((size_t)(b * NKV + kv) * SS + s) * HD + d] = val;
        return;
    }
    const bool isq = (head < NH);
    const float* row = qkv + (size_t)bs * QKVD +
                       (isq ? head * HD : DIM + (head - NH) * HD);
    float val = row[d];

    __shared__ float red[4];
    __shared__ float xs[HD];
    float sq = val * val;
#pragma unroll
    for (int o = 16; o > 0; o >>= 1) sq += __shfl_xor_sync(0xffffffffu, sq, o);
    if ((d & 31) == 0) red[d >> 5] = sq;
    __syncthreads();
    float ms = (red[0] + red[1] + red[2] + red[3]) * (1.0f / HD);
    float xn = val * rsqrtf(ms + 1.1920929e-07f);
    xs[d] = xn;
    __syncthreads();

    float outv;
    if (d < 64) {
        int f = d & 31;
        double inv = pow(10000.0, -(double)f / 32.0);
        double ang = (double)s * inv;
        double sd, cd;
        sincos(ang, &sd, &cd);
        float c = (float)cd, sn = (float)sd;
        float x1 = xs[f], x2 = xs[f + 32];
        outv = (d < 32) ? (x1 * c + x2 * sn) : (-x1 * sn + x2 * c);
    } else {
        outv = xn;
    }

    if (isq) {
        outv *= q_gain[head];
        q[((size_t)(b * NH + head) * SS + s) * HD + d] = outv;
    } else {
        int kv = head - NH;
        k[((size_t)(b * NKV + kv) * SS + s) * HD + d] = outv;
    }
}

// =====================================================================
// Causal flash attention, fp32. grid (S/64, NH, B), 256 threads.
// 64-row Q tile; loop kv tiles 0..qt with online softmax.
// =====================================================================
#define ABM 64
#define ABN 64
#define ATTN_SMEM_FLOATS (64*128 + 128*64 + 64*128 + 64*65 + 3*64)

__global__ __launch_bounds__(256, 1)
void attn_kernel(const float* __restrict__ q, const float* __restrict__ k,
                 const float* __restrict__ v, float* __restrict__ y)
{
    extern __shared__ float sm[];
    float* Qs   = sm;                    // [64][128]
    float* Kst  = Qs  + 64 * 128;        // [128][64] transposed
    float* Vs   = Kst + 128 * 64;        // [64][128]
    float* Ps   = Vs  + 64 * 128;        // [64][65]
    float* m_s  = Ps  + 64 * 65;
    float* l_s  = m_s + 64;
    float* al_s = l_s + 64;

    const int qt = blockIdx.x, h = blockIdx.y, b = blockIdx.z;
    const int kvh = h >> 2;              // GQA: 4 q-heads per kv-head
    const int tid = threadIdx.x;
    const int tx = tid & 15, ty = tid >> 4;
    const float scale = 0.08838834764831845f;  // 1/sqrt(128)

    const float* qbase = q + ((size_t)(b * NH + h) * SS + qt * ABM) * HD;
    const float* kbase = k + ((size_t)(b * NKV + kvh) * SS) * HD;
    const float* vbase = v + ((size_t)(b * NKV + kvh) * SS) * HD;

    // load Q tile (2048 float4)
#pragma unroll
    for (int r = 0; r < 8; r++) {
        int f4 = tid + 256 * r;
        int row = f4 >> 5, dc = (f4 & 31) * 4;
        *(float4*)(Qs + row * HD + dc) = *(const float4*)(qbase + row * HD + dc);
    }
    if (tid < 64) { m_s[tid] = -1e30f; l_s[tid] = 0.f; }

    float acc[32];
#pragma unroll
    for (int c = 0; c < 32; c++) acc[c] = 0.f;
    const int prow = tid >> 2;
    const int pcol = (tid & 3) * 32;
    __syncthreads();

    for (int kvt = 0; kvt <= qt; kvt++) {
        // load K (transposed into Kst) and V
#pragma unroll
        for (int r = 0; r < 8; r++) {
            int f4 = tid * 8 + r;
            int row = f4 >> 5, dc = (f4 & 31) * 4;
            float4 k4 = *(const float4*)(kbase + (size_t)(kvt * ABN + row) * HD + dc);
            Kst[(dc + 0) * 64 + row] = k4.x;
            Kst[(dc + 1) * 64 + row] = k4.y;
            Kst[(dc + 2) * 64 + row] = k4.z;
            Kst[(dc + 3) * 64 + row] = k4.w;
            float4 v4 = *(const float4*)(vbase + (size_t)(kvt * ABN + row) * HD + dc);
            *(float4*)(Vs + row * HD + dc) = v4;
        }
        __syncthreads();

        // S = Q K^T (4x4 microtile)
        float sacc[4][4];
#pragma unroll
        for (int i = 0; i < 4; i++)
#pragma unroll
            for (int j = 0; j < 4; j++) sacc[i][j] = 0.f;

        for (int kk = 0; kk < HD; kk++) {
            float a[4], bb[4];
#pragma unroll
            for (int i = 0; i < 4; i++) a[i] = Qs[(ty + 16 * i) * HD + kk];
#pragma unroll
            for (int j = 0; j < 4; j++) bb[j] = Kst[kk * 64 + tx + 16 * j];
#pragma unroll
            for (int i = 0; i < 4; i++)
#pragma unroll
                for (int j = 0; j < 4; j++) sacc[i][j] += a[i] * bb[j];
        }

        const bool diag = (kvt == qt);
#pragma unroll
        for (int i = 0; i < 4; i++)
#pragma unroll
            for (int j = 0; j < 4; j++) {
                float sv = sacc[i][j] * scale;
                if (diag && (tx + 16 * j > ty + 16 * i)) sv = -1e30f;
                sacc[i][j] = sv;
            }

        // online softmax (each row owned by 16 threads with same ty)
#pragma unroll
        for (int i = 0; i < 4; i++) {
            int r = ty + 16 * i;
            float rm = fmaxf(fmaxf(sacc[i][0], sacc[i][1]),
                             fmaxf(sacc[i][2], sacc[i][3]));
#pragma unroll
            for (int o = 1; o < 16; o <<= 1)
                rm = fmaxf(rm, __shfl_xor_sync(0xffffffffu, rm, o));
            float mold = m_s[r];
            float mnew = fmaxf(mold, rm);
            float rs = 0.f;
#pragma unroll
            for (int j = 0; j < 4; j++) {
                float p = expf(sacc[i][j] - mnew);
                Ps[r * 65 + tx + 16 * j] = p;
                rs += p;
            }
#pragma unroll
            for (int o = 1; o < 16; o <<= 1)
                rs += __shfl_xor_sync(0xffffffffu, rs, o);
            if (tx == 0) {
                float alpha = expf(mold - mnew);
                al_s[r] = alpha;
                m_s[r]  = mnew;
                l_s[r]  = l_s[r] * alpha + rs;
            }
        }
        __syncthreads();

        // O += P V  (thread owns 1 row x 32 cols)
        float al = al_s[prow];
#pragma unroll
        for (int c = 0; c < 32; c++) acc[c] *= al;
        for (int j = 0; j < 64; j++) {
            float p = Ps[prow * 65 + j];
            const float* vr = Vs + j * HD + pcol;
#pragma unroll
            for (int c = 0; c < 32; c += 4) {
                float4 v4 = *(const float4*)(vr + c);
                acc[c]     += p * v4.x;
                acc[c + 1] += p * v4.y;
                acc[c + 2] += p * v4.z;
                acc[c + 3] += p * v4.w;
            }
        }
        __syncthreads();
    }

    // normalize and write y[b][s][h*128 + c]
    float linv = 1.0f / l_s[prow];
    float* yrow = y + ((size_t)b * SS + qt * ABM + prow) * DIM + h * HD + pcol;
#pragma unroll
    for (int c = 0; c < 32; c += 4) {
        float4 o4 = make_float4(acc[c] * linv, acc[c + 1] * linv,
                                acc[c + 2] * linv, acc[c + 3] * linv);
        *(float4*)(yrow + c) = o4;
    }
}

// =====================================================================
// host
// =====================================================================
extern "C" void kernel_launch(void* const* d_in, const int* in_sizes, int n_in,
                              void* d_out, int out_size)
{
    const float* x     = (const float*)d_in[0];
    const float* Wq    = (const float*)d_in[1];
    const float* Wk    = (const float*)d_in[2];
    const float* Wv    = (const float*)d_in[3];
    const float* Wproj = (const float*)d_in[4];
    const float* qg    = (const float*)d_in[5];
    float* out = (float*)d_out;

    float *qkv, *q, *k, *v, *y;
    cudaGetSymbolAddress((void**)&qkv, g_qkv);
    cudaGetSymbolAddress((void**)&q,   g_q);
    cudaGetSymbolAddress((void**)&k,   g_k);
    cudaGetSymbolAddress((void**)&v,   g_v);
    cudaGetSymbolAddress((void**)&y,   g_y);

    cudaFuncSetAttribute(attn_kernel,
                         cudaFuncAttributeMaxDynamicSharedMemorySize,
                         ATTN_SMEM_FLOATS * sizeof(float));

    // 1) QKV projections into g_qkv (ldc = 3072)
    gemm_nt<<<dim3(DIM / 128, MROWS / 128), 256>>>(x, Wq, qkv, MROWS, DIM, DIM, QKVD, 0);
    gemm_nt<<<dim3(KVD / 128, MROWS / 128), 256>>>(x, Wk, qkv, MROWS, KVD, DIM, QKVD, DIM);
    gemm_nt<<<dim3(KVD / 128, MROWS / 128), 256>>>(x, Wv, qkv, MROWS, KVD, DIM, QKVD, DIM + KVD);

    // 2) RMS-norm + RoPE + gain + reshape
    norm_rope<<<dim3(BB * SS, NH + 2 * NKV), 128>>>(qkv, qg, q, k, v);

    // 3) causal flash attention -> g_y
    attn_kernel<<<dim3(SS / ABM, NH, BB), 256,
                  ATTN_SMEM_FLOATS * sizeof(float)>>>(q, k, v, y);

    // 4) output projection -> d_out
    gemm_nt<<<dim3(DIM / 128, MROWS / 128), 256>>>(y, Wproj, out, MROWS, DIM, DIM, DIM, 0);
}

// round 3
// speedup vs baseline: 1.2019x; 1.2005x over previous
#include <cuda_runtime.h>
#include <math.h>
#include <stdint.h>

#define DIM 2048
#define NH 16
#define NKV 4
#define HD 128
#define BB 4
#define SS 2048
#define KVD 512        // NKV*HD
#define QKVD 3072      // DIM + 2*KVD
#define MROWS (BB*SS)  // 8192

// ---------------- scratch (no allocations allowed) ----------------
__device__ float g_qkv[(size_t)BB*SS*QKVD];   // 100.7 MB
__device__ float g_q[(size_t)BB*NH*SS*HD];    // 67 MB
__device__ float g_k[(size_t)BB*NKV*SS*HD];   // 16.8 MB
__device__ float g_v[(size_t)BB*NKV*SS*HD];   // 16.8 MB
__device__ float g_y[(size_t)BB*SS*DIM];      // 67 MB

// =====================================================================
// tf32 helpers
// =====================================================================
__device__ __forceinline__ uint32_t f2tf32(float f) {
    uint32_t r;
    asm("cvt.rna.tf32.f32 %0, %1;" : "=r"(r) : "f"(f));
    return r;
}

__device__ __forceinline__ void mma_tf32(float* c, const uint32_t* a,
                                         uint32_t b0, uint32_t b1) {
    asm volatile(
        "mma.sync.aligned.m16n8k8.row.col.f32.tf32.tf32.f32 "
        "{%0,%1,%2,%3}, {%4,%5,%6,%7}, {%8,%9}, {%0,%1,%2,%3};"
        : "+f"(c[0]), "+f"(c[1]), "+f"(c[2]), "+f"(c[3])
        : "r"(a[0]), "r"(a[1]), "r"(a[2]), "r"(a[3]), "r"(b0), "r"(b1));
}

// =====================================================================
// tf32 tensor-core GEMM: C[m, coloff+n] = sum_k A[m,k] * W[n,k]
// A row-major MxK, W row-major NxK (so logical B = W^T, col-major = W rows).
// 128x128x32 tiles, 256 threads (8 warps, 4x2), warp tile 32x64,
// m16n8k8 tf32 HMMA. Inputs converted to tf32 at the smem store.
// =====================================================================
__global__ __launch_bounds__(256, 2)
void gemm_tf32(const float* __restrict__ A, const float* __restrict__ W,
               float* __restrict__ C, int M, int N, int K, int ldc, int coloff)
{
    __shared__ uint32_t As[128][36];   // [m][k], padded: bank = (4g+t) distinct
    __shared__ uint32_t Bs[32][136];   // [k][n], padded: bank = (8t+g) distinct

    const int tid  = threadIdx.x;
    const int lane = tid & 31;
    const int wid  = tid >> 5;
    const int wm   = wid & 3;          // 0..3 -> 32-row slabs
    const int wn   = wid >> 2;         // 0..1 -> 64-col slabs
    const int g    = lane >> 2;        // group 0..7
    const int t    = lane & 3;         // 0..3
    const int m0   = blockIdx.y * 128;
    const int n0   = blockIdx.x * 128;

    float acc[2][8][4];
#pragma unroll
    for (int mt = 0; mt < 2; mt++)
#pragma unroll
        for (int nt = 0; nt < 8; nt++)
#pragma unroll
            for (int c = 0; c < 4; c++) acc[mt][nt][c] = 0.f;

    for (int k0 = 0; k0 < K; k0 += 32) {
        // load A tile 128x32 (1024 float4 -> 4 per thread), cvt to tf32
#pragma unroll
        for (int r = 0; r < 4; r++) {
            int f4  = tid + 256 * r;
            int row = f4 >> 3;
            int c4  = (f4 & 7) * 4;
            float4 v = *(const float4*)(A + (size_t)(m0 + row) * K + k0 + c4);
            As[row][c4 + 0] = f2tf32(v.x);
            As[row][c4 + 1] = f2tf32(v.y);
            As[row][c4 + 2] = f2tf32(v.z);
            As[row][c4 + 3] = f2tf32(v.w);
        }
        // load W tile 128x32, transpose into Bs[k][n], cvt to tf32
#pragma unroll
        for (int r = 0; r < 4; r++) {
            int f4  = tid + 256 * r;
            int row = f4 >> 3;
            int c4  = (f4 & 7) * 4;
            float4 v = *(const float4*)(W + (size_t)(n0 + row) * K + k0 + c4);
            Bs[c4 + 0][row] = f2tf32(v.x);
            Bs[c4 + 1][row] = f2tf32(v.y);
            Bs[c4 + 2][row] = f2tf32(v.z);
            Bs[c4 + 3][row] = f2tf32(v.w);
        }
        __syncthreads();

#pragma unroll
        for (int kc = 0; kc < 4; kc++) {
            const int kb = kc * 8;
            uint32_t a[2][4];
#pragma unroll
            for (int mt = 0; mt < 2; mt++) {
                int rb = wm * 32 + mt * 16;
                a[mt][0] = As[rb + g    ][kb + t    ];
                a[mt][1] = As[rb + g + 8][kb + t    ];
                a[mt][2] = As[rb + g    ][kb + t + 4];
                a[mt][3] = As[rb + g + 8][kb + t + 4];
            }
#pragma unroll
            for (int nt = 0; nt < 8; nt++) {
                int nb = wn * 64 + nt * 8 + g;
                uint32_t b0 = Bs[kb + t    ][nb];
                uint32_t b1 = Bs[kb + t + 4][nb];
                mma_tf32(acc[0][nt], a[0], b0, b1);
                mma_tf32(acc[1][nt], a[1], b0, b1);
            }
        }
        __syncthreads();
    }

    // epilogue: c0/c1 at (g, 2t), (g, 2t+1); c2/c3 at row+8
#pragma unroll
    for (int mt = 0; mt < 2; mt++) {
        int row = m0 + wm * 32 + mt * 16 + g;
#pragma unroll
        for (int nt = 0; nt < 8; nt++) {
            int col = coloff + n0 + wn * 64 + nt * 8 + 2 * t;
            float2 v01 = make_float2(acc[mt][nt][0], acc[mt][nt][1]);
            float2 v23 = make_float2(acc[mt][nt][2], acc[mt][nt][3]);
            *(float2*)(C + (size_t)row * ldc + col)       = v01;
            *(float2*)(C + (size_t)(row + 8) * ldc + col) = v23;
        }
    }
}

// =====================================================================
// RMS-norm + RoPE + gain + reshape into [B, heads, S, hd] layouts.
// grid: x = B*S, y = NH + 2*NKV (q heads | k heads | v copy). block 128.
// =====================================================================
__global__ void norm_rope(const float* __restrict__ qkv,
                          const float* __restrict__ q_gain,
                          float* __restrict__ q, float* __restrict__ k,
                          float* __restrict__ v)
{
    const int bs   = blockIdx.x;
    const int head = blockIdx.y;
    const int b = bs / SS, s = bs % SS;
    const int d = threadIdx.x;

    if (head >= NH + NKV) {            // V: pure copy/reshape
        int kv = head - NH - NKV;
        float val = qkv[(size_t)bs * QKVD + DIM + KVD + kv * HD + d];
        v[((size_t)(b * NKV + kv) * SS + s) * HD + d] = val;
        return;
    }
    const bool isq = (head < NH);
    const float* row = qkv + (size_t)bs * QKVD +
                       (isq ? head * HD : DIM + (head - NH) * HD);
    float val = row[d];

    __shared__ float red[4];
    __shared__ float xs[HD];
    float sq = val * val;
#pragma unroll
    for (int o = 16; o > 0; o >>= 1) sq += __shfl_xor_sync(0xffffffffu, sq, o);
    if ((d & 31) == 0) red[d >> 5] = sq;
    __syncthreads();
    float ms = (red[0] + red[1] + red[2] + red[3]) * (1.0f / HD);
    float xn = val * rsqrtf(ms + 1.1920929e-07f);
    xs[d] = xn;
    __syncthreads();

    float outv;
    if (d < 64) {
        int f = d & 31;
        double inv = pow(10000.0, -(double)f / 32.0);
        double ang = (double)s * inv;
        double sd, cd;
        sincos(ang, &sd, &cd);
        float c = (float)cd, sn = (float)sd;
        float x1 = xs[f], x2 = xs[f + 32];
        outv = (d < 32) ? (x1 * c + x2 * sn) : (-x1 * sn + x2 * c);
    } else {
        outv = xn;
    }

    if (isq) {
        outv *= q_gain[head];
        q[((size_t)(b * NH + head) * SS + s) * HD + d] = outv;
    } else {
        int kv = head - NH;
        k[((size_t)(b * NKV + kv) * SS + s) * HD + d] = outv;
    }
}

// =====================================================================
// Causal flash attention, fp32. grid (S/64, NH, B), 256 threads.
// 64-row Q tile; loop kv tiles 0..qt with online softmax.
// =====================================================================
#define ABM 64
#define ABN 64
#define ATTN_SMEM_FLOATS (64*128 + 128*64 + 64*128 + 64*65 + 3*64)

__global__ __launch_bounds__(256, 1)
void attn_kernel(const float* __restrict__ q, const float* __restrict__ k,
                 const float* __restrict__ v, float* __restrict__ y)
{
    extern __shared__ float sm[];
    float* Qs   = sm;                    // [64][128]
    float* Kst  = Qs  + 64 * 128;        // [128][64] transposed
    float* Vs   = Kst + 128 * 64;        // [64][128]
    float* Ps   = Vs  + 64 * 128;        // [64][65]
    float* m_s  = Ps  + 64 * 65;
    float* l_s  = m_s + 64;
    float* al_s = l_s + 64;

    const int qt = blockIdx.x, h = blockIdx.y, b = blockIdx.z;
    const int kvh = h >> 2;              // GQA: 4 q-heads per kv-head
    const int tid = threadIdx.x;
    const int tx = tid & 15, ty = tid >> 4;
    const float scale = 0.08838834764831845f;  // 1/sqrt(128)

    const float* qbase = q + ((size_t)(b * NH + h) * SS + qt * ABM) * HD;
    const float* kbase = k + ((size_t)(b * NKV + kvh) * SS) * HD;
    const float* vbase = v + ((size_t)(b * NKV + kvh) * SS) * HD;

    // load Q tile (2048 float4)
#pragma unroll
    for (int r = 0; r < 8; r++) {
        int f4 = tid + 256 * r;
        int row = f4 >> 5, dc = (f4 & 31) * 4;
        *(float4*)(Qs + row * HD + dc) = *(const float4*)(qbase + row * HD + dc);
    }
    if (tid < 64) { m_s[tid] = -1e30f; l_s[tid] = 0.f; }

    float acc[32];
#pragma unroll
    for (int c = 0; c < 32; c++) acc[c] = 0.f;
    const int prow = tid >> 2;
    const int pcol = (tid & 3) * 32;
    __syncthreads();

    for (int kvt = 0; kvt <= qt; kvt++) {
        // load K (transposed into Kst) and V
#pragma unroll
        for (int r = 0; r < 8; r++) {
            int f4 = tid * 8 + r;
            int row = f4 >> 5, dc = (f4 & 31) * 4;
            float4 k4 = *(const float4*)(kbase + (size_t)(kvt * ABN + row) * HD + dc);
            Kst[(dc + 0) * 64 + row] = k4.x;
            Kst[(dc + 1) * 64 + row] = k4.y;
            Kst[(dc + 2) * 64 + row] = k4.z;
            Kst[(dc + 3) * 64 + row] = k4.w;
            float4 v4 = *(const float4*)(vbase + (size_t)(kvt * ABN + row) * HD + dc);
            *(float4*)(Vs + row * HD + dc) = v4;
        }
        __syncthreads();

        // S = Q K^T (4x4 microtile)
        float sacc[4][4];
#pragma unroll
        for (int i = 0; i < 4; i++)
#pragma unroll
            for (int j = 0; j < 4; j++) sacc[i][j] = 0.f;

        for (int kk = 0; kk < HD; kk++) {
            float a[4], bb[4];
#pragma unroll
            for (int i = 0; i < 4; i++) a[i] = Qs[(ty + 16 * i) * HD + kk];
#pragma unroll
            for (int j = 0; j < 4; j++) bb[j] = Kst[kk * 64 + tx + 16 * j];
#pragma unroll
            for (int i = 0; i < 4; i++)
#pragma unroll
                for (int j = 0; j < 4; j++) sacc[i][j] += a[i] * bb[j];
        }

        const bool diag = (kvt == qt);
#pragma unroll
        for (int i = 0; i < 4; i++)
#pragma unroll
            for (int j = 0; j < 4; j++) {
                float sv = sacc[i][j] * scale;
                if (diag && (tx + 16 * j > ty + 16 * i)) sv = -1e30f;
                sacc[i][j] = sv;
            }

        // online softmax (each row owned by 16 threads with same ty)
#pragma unroll
        for (int i = 0; i < 4; i++) {
            int r = ty + 16 * i;
            float rm = fmaxf(fmaxf(sacc[i][0], sacc[i][1]),
                             fmaxf(sacc[i][2], sacc[i][3]));
#pragma unroll
            for (int o = 1; o < 16; o <<= 1)
                rm = fmaxf(rm, __shfl_xor_sync(0xffffffffu, rm, o));
            float mold = m_s[r];
            float mnew = fmaxf(mold, rm);
            float rs = 0.f;
#pragma unroll
            for (int j = 0; j < 4; j++) {
                float p = expf(sacc[i][j] - mnew);
                Ps[r * 65 + tx + 16 * j] = p;
                rs += p;
            }
#pragma unroll
            for (int o = 1; o < 16; o <<= 1)
                rs += __shfl_xor_sync(0xffffffffu, rs, o);
            if (tx == 0) {
                float alpha = expf(mold - mnew);
                al_s[r] = alpha;
                m_s[r]  = mnew;
                l_s[r]  = l_s[r] * alpha + rs;
            }
        }
        __syncthreads();

        // O += P V  (thread owns 1 row x 32 cols)
        float al = al_s[prow];
#pragma unroll
        for (int c = 0; c < 32; c++) acc[c] *= al;
        for (int j = 0; j < 64; j++) {
            float p = Ps[prow * 65 + j];
            const float* vr = Vs + j * HD + pcol;
#pragma unroll
            for (int c = 0; c < 32; c += 4) {
                float4 v4 = *(const float4*)(vr + c);
                acc[c]     += p * v4.x;
                acc[c + 1] += p * v4.y;
                acc[c + 2] += p * v4.z;
                acc[c + 3] += p * v4.w;
            }
        }
        __syncthreads();
    }

    // normalize and write y[b][s][h*128 + c]
    float linv = 1.0f / l_s[prow];
    float* yrow = y + ((size_t)b * SS + qt * ABM + prow) * DIM + h * HD + pcol;
#pragma unroll
    for (int c = 0; c < 32; c += 4) {
        float4 o4 = make_float4(acc[c] * linv, acc[c + 1] * linv,
                                acc[c + 2] * linv, acc[c + 3] * linv);
        *(float4*)(yrow + c) = o4;
    }
}

// =====================================================================
// host
// =====================================================================
extern "C" void kernel_launch(void* const* d_in, const int* in_sizes, int n_in,
                              void* d_out, int out_size)
{
    const float* x     = (const float*)d_in[0];
    const float* Wq    = (const float*)d_in[1];
    const float* Wk    = (const float*)d_in[2];
    const float* Wv    = (const float*)d_in[3];
    const float* Wproj = (const float*)d_in[4];
    const float* qg    = (const float*)d_in[5];
    float* out = (float*)d_out;

    float *qkv, *q, *k, *v, *y;
    cudaGetSymbolAddress((void**)&qkv, g_qkv);
    cudaGetSymbolAddress((void**)&q,   g_q);
    cudaGetSymbolAddress((void**)&k,   g_k);
    cudaGetSymbolAddress((void**)&v,   g_v);
    cudaGetSymbolAddress((void**)&y,   g_y);

    cudaFuncSetAttribute(attn_kernel,
                         cudaFuncAttributeMaxDynamicSharedMemorySize,
                         ATTN_SMEM_FLOATS * sizeof(float));

    // 1) QKV projections into g_qkv (ldc = 3072), tf32 tensor cores
    gemm_tf32<<<dim3(DIM / 128, MROWS / 128), 256>>>(x, Wq, qkv, MROWS, DIM, DIM, QKVD, 0);
    gemm_tf32<<<dim3(KVD / 128, MROWS / 128), 256>>>(x, Wk, qkv, MROWS, KVD, DIM, QKVD, DIM);
    gemm_tf32<<<dim3(KVD / 128, MROWS / 128), 256>>>(x, Wv, qkv, MROWS, KVD, DIM, QKVD, DIM + KVD);

    // 2) RMS-norm + RoPE + gain + reshape
    norm_rope<<<dim3(BB * SS, NH + 2 * NKV), 128>>>(qkv, qg, q, k, v);

    // 3) causal flash attention -> g_y
    attn_kernel<<<dim3(SS / ABM, NH, BB), 256,
                  ATTN_SMEM_FLOATS * sizeof(float)>>>(q, k, v, y);

    // 4) output projection -> d_out, tf32 tensor cores
    gemm_tf32<<<dim3(DIM / 128, MROWS / 128), 256>>>(y, Wproj, out, MROWS, DIM, DIM, DIM, 0);
}

// round 4
// speedup vs baseline: 6.5569x; 5.4554x over previous
#include <cuda_runtime.h>
#include <math.h>
#include <stdint.h>

#define DIM 2048
#define NH 16
#define NKV 4
#define HD 128
#define BB 4
#define SS 2048
#define KVD 512        // NKV*HD
#define QKVD 3072      // DIM + 2*KVD
#define MROWS (BB*SS)  // 8192

// ---------------- scratch (no allocations allowed) ----------------
__device__ float g_qkv[(size_t)BB*SS*QKVD];   // 100.7 MB
__device__ float g_q[(size_t)BB*NH*SS*HD];    // 67 MB
__device__ float g_k[(size_t)BB*NKV*SS*HD];   // 16.8 MB
__device__ float g_v[(size_t)BB*NKV*SS*HD];   // 16.8 MB
__device__ float g_y[(size_t)BB*SS*DIM];      // 67 MB
__device__ float g_cosr[SS*32];
__device__ float g_sinr[SS*32];

// =====================================================================
// tf32 helpers
// =====================================================================
__device__ __forceinline__ uint32_t f2tf32(float f) {
    uint32_t r;
    asm("cvt.rna.tf32.f32 %0, %1;" : "=r"(r) : "f"(f));
    return r;
}

__device__ __forceinline__ void mma_tf32(float* c, const uint32_t* a,
                                         uint32_t b0, uint32_t b1) {
    asm volatile(
        "mma.sync.aligned.m16n8k8.row.col.f32.tf32.tf32.f32 "
        "{%0,%1,%2,%3}, {%4,%5,%6,%7}, {%8,%9}, {%0,%1,%2,%3};"
        : "+f"(c[0]), "+f"(c[1]), "+f"(c[2]), "+f"(c[3])
        : "r"(a[0]), "r"(a[1]), "r"(a[2]), "r"(a[3]), "r"(b0), "r"(b1));
}

// =====================================================================
// tf32 tensor-core GEMM (unchanged from R2)
// =====================================================================
__global__ __launch_bounds__(256, 2)
void gemm_tf32(const float* __restrict__ A, const float* __restrict__ W,
               float* __restrict__ C, int M, int N, int K, int ldc, int coloff)
{
    __shared__ uint32_t As[128][36];
    __shared__ uint32_t Bs[32][136];

    const int tid  = threadIdx.x;
    const int lane = tid & 31;
    const int wid  = tid >> 5;
    const int wm   = wid & 3;
    const int wn   = wid >> 2;
    const int g    = lane >> 2;
    const int t    = lane & 3;
    const int m0   = blockIdx.y * 128;
    const int n0   = blockIdx.x * 128;

    float acc[2][8][4];
#pragma unroll
    for (int mt = 0; mt < 2; mt++)
#pragma unroll
        for (int nt = 0; nt < 8; nt++)
#pragma unroll
            for (int c = 0; c < 4; c++) acc[mt][nt][c] = 0.f;

    for (int k0 = 0; k0 < K; k0 += 32) {
#pragma unroll
        for (int r = 0; r < 4; r++) {
            int f4  = tid + 256 * r;
            int row = f4 >> 3;
            int c4  = (f4 & 7) * 4;
            float4 v = *(const float4*)(A + (size_t)(m0 + row) * K + k0 + c4);
            As[row][c4 + 0] = f2tf32(v.x);
            As[row][c4 + 1] = f2tf32(v.y);
            As[row][c4 + 2] = f2tf32(v.z);
            As[row][c4 + 3] = f2tf32(v.w);
        }
#pragma unroll
        for (int r = 0; r < 4; r++) {
            int f4  = tid + 256 * r;
            int row = f4 >> 3;
            int c4  = (f4 & 7) * 4;
            float4 v = *(const float4*)(W + (size_t)(n0 + row) * K + k0 + c4);
            Bs[c4 + 0][row] = f2tf32(v.x);
            Bs[c4 + 1][row] = f2tf32(v.y);
            Bs[c4 + 2][row] = f2tf32(v.z);
            Bs[c4 + 3][row] = f2tf32(v.w);
        }
        __syncthreads();

#pragma unroll
        for (int kc = 0; kc < 4; kc++) {
            const int kb = kc * 8;
            uint32_t a[2][4];
#pragma unroll
            for (int mt = 0; mt < 2; mt++) {
                int rb = wm * 32 + mt * 16;
                a[mt][0] = As[rb + g    ][kb + t    ];
                a[mt][1] = As[rb + g + 8][kb + t    ];
                a[mt][2] = As[rb + g    ][kb + t + 4];
                a[mt][3] = As[rb + g + 8][kb + t + 4];
            }
#pragma unroll
            for (int nt = 0; nt < 8; nt++) {
                int nb = wn * 64 + nt * 8 + g;
                uint32_t b0 = Bs[kb + t    ][nb];
                uint32_t b1 = Bs[kb + t + 4][nb];
                mma_tf32(acc[0][nt], a[0], b0, b1);
                mma_tf32(acc[1][nt], a[1], b0, b1);
            }
        }
        __syncthreads();
    }

#pragma unroll
    for (int mt = 0; mt < 2; mt++) {
        int row = m0 + wm * 32 + mt * 16 + g;
#pragma unroll
        for (int nt = 0; nt < 8; nt++) {
            int col = coloff + n0 + wn * 64 + nt * 8 + 2 * t;
            float2 v01 = make_float2(acc[mt][nt][0], acc[mt][nt][1]);
            float2 v23 = make_float2(acc[mt][nt][2], acc[mt][nt][3]);
            *(float2*)(C + (size_t)row * ldc + col)       = v01;
            *(float2*)(C + (size_t)(row + 8) * ldc + col) = v23;
        }
    }
}

// =====================================================================
// RoPE table init (once per graph replay; cheap)
// =====================================================================
__global__ void rope_init()
{
    int i = blockIdx.x * blockDim.x + threadIdx.x;   // SS*32 threads
    int s = i >> 5, f = i & 31;
    double inv = pow(10000.0, -(double)f / 32.0);
    double ang = (double)s * inv;
    double sd, cd;
    sincos(ang, &sd, &cd);
    g_cosr[i] = (float)cd;
    g_sinr[i] = (float)sd;
}

// =====================================================================
// RMS-norm + RoPE (table) + gain + reshape
// =====================================================================
__global__ void norm_rope(const float* __restrict__ qkv,
                          const float* __restrict__ q_gain,
                          float* __restrict__ q, float* __restrict__ k,
                          float* __restrict__ v)
{
    const int bs   = blockIdx.x;
    const int head = blockIdx.y;
    const int b = bs / SS, s = bs % SS;
    const int d = threadIdx.x;

    if (head >= NH + NKV) {            // V: pure copy/reshape
        int kv = head - NH - NKV;
        float val = qkv[(size_t)bs * QKVD + DIM + KVD + kv * HD + d];
        v[((size_t)(b * NKV + kv) * SS + s) * HD + d] = val;
        return;
    }
    const bool isq = (head < NH);
    const float* row = qkv + (size_t)bs * QKVD +
                       (isq ? head * HD : DIM + (head - NH) * HD);
    float val = row[d];

    __shared__ float red[4];
    __shared__ float xs[HD];
    float sq = val * val;
#pragma unroll
    for (int o = 16; o > 0; o >>= 1) sq += __shfl_xor_sync(0xffffffffu, sq, o);
    if ((d & 31) == 0) red[d >> 5] = sq;
    __syncthreads();
    float ms = (red[0] + red[1] + red[2] + red[3]) * (1.0f / HD);
    float xn = val * rsqrtf(ms + 1.1920929e-07f);
    xs[d] = xn;
    __syncthreads();

    float outv;
    if (d < 64) {
        int f = d & 31;
        float c  = g_cosr[s * 32 + f];
        float sn = g_sinr[s * 32 + f];
        float x1 = xs[f], x2 = xs[f + 32];
        outv = (d < 32) ? (x1 * c + x2 * sn) : (-x1 * sn + x2 * c);
    } else {
        outv = xn;
    }

    if (isq) {
        outv *= q_gain[head];
        q[((size_t)(b * NH + head) * SS + s) * HD + d] = outv;
    } else {
        int kv = head - NH;
        k[((size_t)(b * NKV + kv) * SS + s) * HD + d] = outv;
    }
}

// =====================================================================
// tf32 tensor-core flash attention. grid (S/64, NH, B), 256 thr, 8 warps.
// Warp grid for S (64x64): wm (4 x 16 rows) x wn (2 x 32 cols).
// For PV (64x128): wm rows, wn * 64 cols (8 n8-tiles).
// Smem strides: A-operands pad to ==4 mod 32, B-operands to ==8 mod 32.
// Double-buffered K/V with register-staged prefetch.
// =====================================================================
#define QS_OFF   0
#define KN_OFF0  8448            // 64*132
#define KN_OFF1  16896
#define VS_OFF0  25344           // 64*136
#define VS_OFF1  34048
#define PS_OFF   42752           // 64*68
#define ST_OFF   47104           // m_s 64 | l_s 64 | pmax 128 | psum 128
#define ATTN_SMEM_WORDS 47488
#define ATTN_SCALE 0.08838834764831845f

__global__ __launch_bounds__(256, 1)
void attn_mma(const float* __restrict__ q, const float* __restrict__ k,
              const float* __restrict__ v, float* __restrict__ y)
{
    extern __shared__ uint32_t sm[];
    float* m_s  = (float*)(sm + ST_OFF);
    float* l_s  = m_s + 64;
    float* pmax = l_s + 64;       // [2][64]
    float* psum = pmax + 128;     // [2][64]

    const int qt = blockIdx.x, h = blockIdx.y, b = blockIdx.z;
    const int kvh = h >> 2;
    const int tid  = threadIdx.x;
    const int lane = tid & 31;
    const int wid  = tid >> 5;
    const int g  = lane >> 2;
    const int t  = lane & 3;
    const int wm = wid & 3;
    const int wn = wid >> 2;

    const float* qbase = q + ((size_t)(b * NH + h) * SS + qt * 64) * HD;
    const float* kbase = k + ((size_t)(b * NKV + kvh) * SS) * HD;
    const float* vbase = v + ((size_t)(b * NKV + kvh) * SS) * HD;

    // ---- load Q tile (scale folded), K0, V0 ----
#pragma unroll
    for (int r = 0; r < 8; r++) {
        int f4 = tid + 256 * r;
        int row = f4 >> 5, c4 = (f4 & 31) * 4;
        float4 v4 = *(const float4*)(qbase + row * HD + c4);
        uint4 u = make_uint4(f2tf32(v4.x * ATTN_SCALE), f2tf32(v4.y * ATTN_SCALE),
                             f2tf32(v4.z * ATTN_SCALE), f2tf32(v4.w * ATTN_SCALE));
        *(uint4*)(sm + QS_OFF + row * 132 + c4) = u;
        float4 k4 = *(const float4*)(kbase + row * HD + c4);
        uint4 uk = make_uint4(f2tf32(k4.x), f2tf32(k4.y), f2tf32(k4.z), f2tf32(k4.w));
        *(uint4*)(sm + KN_OFF0 + row * 132 + c4) = uk;
        float4 w4 = *(const float4*)(vbase + row * HD + c4);
        uint4 uv = make_uint4(f2tf32(w4.x), f2tf32(w4.y), f2tf32(w4.z), f2tf32(w4.w));
        *(uint4*)(sm + VS_OFF0 + row * 136 + c4) = uv;
    }
    if (tid < 64) { m_s[tid] = -1e30f; l_s[tid] = 0.f; }

    float oacc[8][4];
#pragma unroll
    for (int nt = 0; nt < 8; nt++)
#pragma unroll
        for (int c = 0; c < 4; c++) oacc[nt][c] = 0.f;

    const int r0 = wm * 16 + g;
    const int r1 = r0 + 8;
    __syncthreads();

    for (int kvt = 0; kvt <= qt; kvt++) {
        const int cur = kvt & 1;
        const bool pre = (kvt < qt);

        // 1) issue prefetch LDG for tile kvt+1
        float4 pk[8], pv[8];
        if (pre) {
            const float* kn = kbase + (size_t)(kvt + 1) * 64 * HD;
            const float* vn = vbase + (size_t)(kvt + 1) * 64 * HD;
#pragma unroll
            for (int r = 0; r < 8; r++) {
                int f4 = tid + 256 * r;
                int row = f4 >> 5, c4 = (f4 & 31) * 4;
                pk[r] = *(const float4*)(kn + row * HD + c4);
                pv[r] = *(const float4*)(vn + row * HD + c4);
            }
        }

        // 2) S = Q K^T
        float sacc[4][4];
#pragma unroll
        for (int nt = 0; nt < 4; nt++)
#pragma unroll
            for (int c = 0; c < 4; c++) sacc[nt][c] = 0.f;

        const uint32_t* Qb = sm + QS_OFF + (wm * 16) * 132;
        const uint32_t* Kb = sm + (cur ? KN_OFF1 : KN_OFF0) + (wn * 32) * 132;
#pragma unroll
        for (int ks = 0; ks < 16; ks++) {
            const int kb = ks * 8;
            uint32_t a[4];
            a[0] = Qb[g * 132 + kb + t];
            a[1] = Qb[(g + 8) * 132 + kb + t];
            a[2] = Qb[g * 132 + kb + t + 4];
            a[3] = Qb[(g + 8) * 132 + kb + t + 4];
#pragma unroll
            for (int nt = 0; nt < 4; nt++) {
                uint32_t b0 = Kb[(nt * 8 + g) * 132 + kb + t];
                uint32_t b1 = Kb[(nt * 8 + g) * 132 + kb + t + 4];
                mma_tf32(sacc[nt], a, b0, b1);
            }
        }

        // 3) causal mask (diagonal tile only) + warp-partial row max
        if (kvt == qt) {
#pragma unroll
            for (int nt = 0; nt < 4; nt++) {
                int cl = wn * 32 + nt * 8 + 2 * t;
                if (cl     > r0) sacc[nt][0] = -1e30f;
                if (cl + 1 > r0) sacc[nt][1] = -1e30f;
                if (cl     > r1) sacc[nt][2] = -1e30f;
                if (cl + 1 > r1) sacc[nt][3] = -1e30f;
            }
        }
        float rmax0 = -1e30f, rmax1 = -1e30f;
#pragma unroll
        for (int nt = 0; nt < 4; nt++) {
            rmax0 = fmaxf(rmax0, fmaxf(sacc[nt][0], sacc[nt][1]));
            rmax1 = fmaxf(rmax1, fmaxf(sacc[nt][2], sacc[nt][3]));
        }
        rmax0 = fmaxf(rmax0, __shfl_xor_sync(0xffffffffu, rmax0, 1));
        rmax0 = fmaxf(rmax0, __shfl_xor_sync(0xffffffffu, rmax0, 2));
        rmax1 = fmaxf(rmax1, __shfl_xor_sync(0xffffffffu, rmax1, 1));
        rmax1 = fmaxf(rmax1, __shfl_xor_sync(0xffffffffu, rmax1, 2));
        if (t == 0) { pmax[wn * 64 + r0] = rmax0; pmax[wn * 64 + r1] = rmax1; }
        __syncthreads();                                   // A

        // 4) softmax: exp, store P (tf32), partial sums, rescale O
        float m_old0 = m_s[r0], m_old1 = m_s[r1];
        float mnew0 = fmaxf(m_old0, fmaxf(pmax[r0], pmax[64 + r0]));
        float mnew1 = fmaxf(m_old1, fmaxf(pmax[r1], pmax[64 + r1]));
        float alpha0 = __expf(m_old0 - mnew0);
        float alpha1 = __expf(m_old1 - mnew1);
        float rs0 = 0.f, rs1 = 0.f;
#pragma unroll
        for (int nt = 0; nt < 4; nt++) {
            float p00 = __expf(sacc[nt][0] - mnew0);
            float p01 = __expf(sacc[nt][1] - mnew0);
            float p10 = __expf(sacc[nt][2] - mnew1);
            float p11 = __expf(sacc[nt][3] - mnew1);
            rs0 += p00 + p01;
            rs1 += p10 + p11;
            int col = wn * 32 + nt * 8 + 2 * t;
            *(uint2*)(sm + PS_OFF + r0 * 68 + col) = make_uint2(f2tf32(p00), f2tf32(p01));
            *(uint2*)(sm + PS_OFF + r1 * 68 + col) = make_uint2(f2tf32(p10), f2tf32(p11));
        }
        rs0 += __shfl_xor_sync(0xffffffffu, rs0, 1);
        rs0 += __shfl_xor_sync(0xffffffffu, rs0, 2);
        rs1 += __shfl_xor_sync(0xffffffffu, rs1, 1);
        rs1 += __shfl_xor_sync(0xffffffffu, rs1, 2);
        if (t == 0) { psum[wn * 64 + r0] = rs0; psum[wn * 64 + r1] = rs1; }
#pragma unroll
        for (int nt = 0; nt < 8; nt++) {
            oacc[nt][0] *= alpha0; oacc[nt][1] *= alpha0;
            oacc[nt][2] *= alpha1; oacc[nt][3] *= alpha1;
        }
        __syncthreads();                                   // B
        if (wn == 0 && t == 0) {
            l_s[r0] = l_s[r0] * alpha0 + psum[r0] + psum[64 + r0];
            l_s[r1] = l_s[r1] * alpha1 + psum[r1] + psum[64 + r1];
            m_s[r0] = mnew0;
            m_s[r1] = mnew1;
        }

        // 5) O += P V
        const uint32_t* Pb = sm + PS_OFF + (wm * 16) * 68;
        const uint32_t* Vb = sm + (cur ? VS_OFF1 : VS_OFF0) + wn * 64;
#pragma unroll
        for (int ks = 0; ks < 8; ks++) {
            const int kb = ks * 8;
            uint32_t a[4];
            a[0] = Pb[g * 68 + kb + t];
            a[1] = Pb[(g + 8) * 68 + kb + t];
            a[2] = Pb[g * 68 + kb + t + 4];
            a[3] = Pb[(g + 8) * 68 + kb + t + 4];
#pragma unroll
            for (int nt = 0; nt < 8; nt++) {
                uint32_t b0 = Vb[(kb + t) * 136 + nt * 8 + g];
                uint32_t b1 = Vb[(kb + t + 4) * 136 + nt * 8 + g];
                mma_tf32(oacc[nt], a, b0, b1);
            }
        }

        // 6) store prefetched K/V into the other slot
        if (pre) {
            uint32_t* Kd = sm + (cur ? KN_OFF0 : KN_OFF1);
            uint32_t* Vd = sm + (cur ? VS_OFF0 : VS_OFF1);
#pragma unroll
            for (int r = 0; r < 8; r++) {
                int f4 = tid + 256 * r;
                int row = f4 >> 5, c4 = (f4 & 31) * 4;
                *(uint4*)(Kd + row * 132 + c4) =
                    make_uint4(f2tf32(pk[r].x), f2tf32(pk[r].y),
                               f2tf32(pk[r].z), f2tf32(pk[r].w));
                *(uint4*)(Vd + row * 136 + c4) =
                    make_uint4(f2tf32(pv[r].x), f2tf32(pv[r].y),
                               f2tf32(pv[r].z), f2tf32(pv[r].w));
            }
        }
        __syncthreads();                                   // C
    }

    // ---- epilogue: normalize, write y[b][s][h*128 + col] ----
    float linv0 = 1.0f / l_s[r0];
    float linv1 = 1.0f / l_s[r1];
    float* y0 = y + ((size_t)b * SS + qt * 64 + r0) * DIM + h * HD + wn * 64;
    float* y1 = y + ((size_t)b * SS + qt * 64 + r1) * DIM + h * HD + wn * 64;
#pragma unroll
    for (int nt = 0; nt < 8; nt++) {
        int col = nt * 8 + 2 * t;
        *(float2*)(y0 + col) = make_float2(oacc[nt][0] * linv0, oacc[nt][1] * linv0);
        *(float2*)(y1 + col) = make_float2(oacc[nt][2] * linv1, oacc[nt][3] * linv1);
    }
}

// =====================================================================
// host
// =====================================================================
extern "C" void kernel_launch(void* const* d_in, const int* in_sizes, int n_in,
                              void* d_out, int out_size)
{
    const float* x     = (const float*)d_in[0];
    const float* Wq    = (const float*)d_in[1];
    const float* Wk    = (const float*)d_in[2];
    const float* Wv    = (const float*)d_in[3];
    const float* Wproj = (const float*)d_in[4];
    const float* qg    = (const float*)d_in[5];
    float* out = (float*)d_out;

    float *qkv, *q, *k, *v, *y;
    cudaGetSymbolAddress((void**)&qkv, g_qkv);
    cudaGetSymbolAddress((void**)&q,   g_q);
    cudaGetSymbolAddress((void**)&k,   g_k);
    cudaGetSymbolAddress((void**)&v,   g_v);
    cudaGetSymbolAddress((void**)&y,   g_y);

    cudaFuncSetAttribute(attn_mma,
                         cudaFuncAttributeMaxDynamicSharedMemorySize,
                         ATTN_SMEM_WORDS * sizeof(uint32_t));

    // 0) RoPE tables
    rope_init<<<SS * 32 / 256, 256>>>();

    // 1) QKV projections into g_qkv (ldc = 3072), tf32 tensor cores
    gemm_tf32<<<dim3(DIM / 128, MROWS / 128), 256>>>(x, Wq, qkv, MROWS, DIM, DIM, QKVD, 0);
    gemm_tf32<<<dim3(KVD / 128, MROWS / 128), 256>>>(x, Wk, qkv, MROWS, KVD, DIM, QKVD, DIM);
    gemm_tf32<<<dim3(KVD / 128, MROWS / 128), 256>>>(x, Wv, qkv, MROWS, KVD, DIM, QKVD, DIM + KVD);

    // 2) RMS-norm + RoPE + gain + reshape
    norm_rope<<<dim3(BB * SS, NH + 2 * NKV), 128>>>(qkv, qg, q, k, v);

    // 3) tf32 tensor-core flash attention -> g_y
    attn_mma<<<dim3(SS / 64, NH, BB), 256,
               ATTN_SMEM_WORDS * sizeof(uint32_t)>>>(q, k, v, y);

    // 4) output projection -> d_out, tf32 tensor cores
    gemm_tf32<<<dim3(DIM / 128, MROWS / 128), 256>>>(y, Wproj, out, MROWS, DIM, DIM, DIM, 0);
}

// round 5
// speedup vs baseline: 7.1194x; 1.0858x over previous
#include <cuda_runtime.h>
#include <math.h>
#include <stdint.h>

#define DIM 2048
#define NH 16
#define NKV 4
#define HD 128
#define BB 4
#define SS 2048
#define KVD 512        // NKV*HD
#define QKVD 3072      // DIM + 2*KVD
#define MROWS (BB*SS)  // 8192
#define ATTN_SCALE 0.08838834764831845f  // 1/sqrt(128)

// ---------------- scratch (no allocations allowed) ----------------
__device__ float g_qkv[(size_t)BB*SS*QKVD];   // 100.7 MB
__device__ float g_q[(size_t)BB*NH*SS*HD];    // tf32 bits (scale folded)
__device__ float g_k[(size_t)BB*NKV*SS*HD];   // tf32 bits
__device__ float g_v[(size_t)BB*NKV*SS*HD];   // tf32 bits
__device__ float g_y[(size_t)BB*SS*DIM];      // 67 MB
__device__ float g_cosr[SS*32];
__device__ float g_sinr[SS*32];

// =====================================================================
// tf32 helpers
// =====================================================================
__device__ __forceinline__ uint32_t f2tf32(float f) {
    uint32_t r;
    asm("cvt.rna.tf32.f32 %0, %1;" : "=r"(r) : "f"(f));
    return r;
}

__device__ __forceinline__ void mma_tf32(float* c, const uint32_t* a,
                                         uint32_t b0, uint32_t b1) {
    asm volatile(
        "mma.sync.aligned.m16n8k8.row.col.f32.tf32.tf32.f32 "
        "{%0,%1,%2,%3}, {%4,%5,%6,%7}, {%8,%9}, {%0,%1,%2,%3};"
        : "+f"(c[0]), "+f"(c[1]), "+f"(c[2]), "+f"(c[3])
        : "r"(a[0]), "r"(a[1]), "r"(a[2]), "r"(a[3]), "r"(b0), "r"(b1));
}

__device__ __forceinline__ void cpa16(uint32_t dst, const void* src) {
    asm volatile("cp.async.cg.shared.global [%0], [%1], 16;"
                 :: "r"(dst), "l"(src));
}

// =====================================================================
// tf32 tensor-core GEMM (unchanged from R2/R3)
// =====================================================================
__global__ __launch_bounds__(256, 2)
void gemm_tf32(const float* __restrict__ A, const float* __restrict__ W,
               float* __restrict__ C, int M, int N, int K, int ldc, int coloff)
{
    __shared__ uint32_t As[128][36];
    __shared__ uint32_t Bs[32][136];

    const int tid  = threadIdx.x;
    const int lane = tid & 31;
    const int wid  = tid >> 5;
    const int wm   = wid & 3;
    const int wn   = wid >> 2;
    const int g    = lane >> 2;
    const int t    = lane & 3;
    const int m0   = blockIdx.y * 128;
    const int n0   = blockIdx.x * 128;

    float acc[2][8][4];
#pragma unroll
    for (int mt = 0; mt < 2; mt++)
#pragma unroll
        for (int nt = 0; nt < 8; nt++)
#pragma unroll
            for (int c = 0; c < 4; c++) acc[mt][nt][c] = 0.f;

    for (int k0 = 0; k0 < K; k0 += 32) {
#pragma unroll
        for (int r = 0; r < 4; r++) {
            int f4  = tid + 256 * r;
            int row = f4 >> 3;
            int c4  = (f4 & 7) * 4;
            float4 v = *(const float4*)(A + (size_t)(m0 + row) * K + k0 + c4);
            As[row][c4 + 0] = f2tf32(v.x);
            As[row][c4 + 1] = f2tf32(v.y);
            As[row][c4 + 2] = f2tf32(v.z);
            As[row][c4 + 3] = f2tf32(v.w);
        }
#pragma unroll
        for (int r = 0; r < 4; r++) {
            int f4  = tid + 256 * r;
            int row = f4 >> 3;
            int c4  = (f4 & 7) * 4;
            float4 v = *(const float4*)(W + (size_t)(n0 + row) * K + k0 + c4);
            Bs[c4 + 0][row] = f2tf32(v.x);
            Bs[c4 + 1][row] = f2tf32(v.y);
            Bs[c4 + 2][row] = f2tf32(v.z);
            Bs[c4 + 3][row] = f2tf32(v.w);
        }
        __syncthreads();

#pragma unroll
        for (int kc = 0; kc < 4; kc++) {
            const int kb = kc * 8;
            uint32_t a[2][4];
#pragma unroll
            for (int mt = 0; mt < 2; mt++) {
                int rb = wm * 32 + mt * 16;
                a[mt][0] = As[rb + g    ][kb + t    ];
                a[mt][1] = As[rb + g + 8][kb + t    ];
                a[mt][2] = As[rb + g    ][kb + t + 4];
                a[mt][3] = As[rb + g + 8][kb + t + 4];
            }
#pragma unroll
            for (int nt = 0; nt < 8; nt++) {
                int nb = wn * 64 + nt * 8 + g;
                uint32_t b0 = Bs[kb + t    ][nb];
                uint32_t b1 = Bs[kb + t + 4][nb];
                mma_tf32(acc[0][nt], a[0], b0, b1);
                mma_tf32(acc[1][nt], a[1], b0, b1);
            }
        }
        __syncthreads();
    }

#pragma unroll
    for (int mt = 0; mt < 2; mt++) {
        int row = m0 + wm * 32 + mt * 16 + g;
#pragma unroll
        for (int nt = 0; nt < 8; nt++) {
            int col = coloff + n0 + wn * 64 + nt * 8 + 2 * t;
            float2 v01 = make_float2(acc[mt][nt][0], acc[mt][nt][1]);
            float2 v23 = make_float2(acc[mt][nt][2], acc[mt][nt][3]);
            *(float2*)(C + (size_t)row * ldc + col)       = v01;
            *(float2*)(C + (size_t)(row + 8) * ldc + col) = v23;
        }
    }
}

// =====================================================================
// RoPE table init
// =====================================================================
__global__ void rope_init()
{
    int i = blockIdx.x * blockDim.x + threadIdx.x;
    int s = i >> 5, f = i & 31;
    double inv = pow(10000.0, -(double)f / 32.0);
    double ang = (double)s * inv;
    double sd, cd;
    sincos(ang, &sd, &cd);
    g_cosr[i] = (float)cd;
    g_sinr[i] = (float)sd;
}

// =====================================================================
// RMS-norm + RoPE + gain + reshape; q/k/v stored as tf32 bits
// (q additionally folded with ATTN_SCALE * q_gain).
// =====================================================================
__global__ void norm_rope(const float* __restrict__ qkv,
                          const float* __restrict__ q_gain,
                          float* __restrict__ q, float* __restrict__ k,
                          float* __restrict__ v)
{
    const int bs   = blockIdx.x;
    const int head = blockIdx.y;
    const int b = bs / SS, s = bs % SS;
    const int d = threadIdx.x;

    if (head >= NH + NKV) {            // V: convert + reshape
        int kv = head - NH - NKV;
        float val = qkv[(size_t)bs * QKVD + DIM + KVD + kv * HD + d];
        v[((size_t)(b * NKV + kv) * SS + s) * HD + d] = __uint_as_float(f2tf32(val));
        return;
    }
    const bool isq = (head < NH);
    const float* row = qkv + (size_t)bs * QKVD +
                       (isq ? head * HD : DIM + (head - NH) * HD);
    float val = row[d];

    __shared__ float red[4];
    __shared__ float xs[HD];
    float sq = val * val;
#pragma unroll
    for (int o = 16; o > 0; o >>= 1) sq += __shfl_xor_sync(0xffffffffu, sq, o);
    if ((d & 31) == 0) red[d >> 5] = sq;
    __syncthreads();
    float ms = (red[0] + red[1] + red[2] + red[3]) * (1.0f / HD);
    float xn = val * rsqrtf(ms + 1.1920929e-07f);
    xs[d] = xn;
    __syncthreads();

    float outv;
    if (d < 64) {
        int f = d & 31;
        float c  = g_cosr[s * 32 + f];
        float sn = g_sinr[s * 32 + f];
        float x1 = xs[f], x2 = xs[f + 32];
        outv = (d < 32) ? (x1 * c + x2 * sn) : (-x1 * sn + x2 * c);
    } else {
        outv = xn;
    }

    if (isq) {
        outv *= q_gain[head] * ATTN_SCALE;
        q[((size_t)(b * NH + head) * SS + s) * HD + d] = __uint_as_float(f2tf32(outv));
    } else {
        int kv = head - NH;
        k[((size_t)(b * NKV + kv) * SS + s) * HD + d] = __uint_as_float(f2tf32(outv));
    }
}

// =====================================================================
// tf32 flash attention, Q tile 128, kv tile 64. 256 thr (8 warps, 4x2).
// cp.async loads (tf32 pre-converted), K single-buffer, V double-buffer,
// named barriers for row-group softmax exchange. grid (16, NH, BB).
// =====================================================================
#define QS_OFF   0            // 128 x 132
#define KS_OFF   16896        // 64 x 132
#define VS_OFF0  25344        // 64 x 136
#define VS_OFF1  34048
#define PS_OFF   42752        // 128 x 68
#define PMAX_OFF 51456        // [2][128]
#define PSUM_OFF 51712        // [2][128]
#define MS_OFF   51968        // [128]
#define LS_OFF   52096        // [128]
#define ATTN_WORDS 52224      // 208,896 bytes

__global__ __launch_bounds__(256, 1)
void attn_mma(const float* __restrict__ q, const float* __restrict__ k,
              const float* __restrict__ v, float* __restrict__ y)
{
    extern __shared__ uint32_t sm[];
    const int qb = (int)gridDim.x - 1 - (int)blockIdx.x;   // heavy CTAs first
    const int h = blockIdx.y, b = blockIdx.z;
    const int kvh = h >> 2;
    const int tid = threadIdx.x;
    const int lane = tid & 31, wid = tid >> 5;
    const int g = lane >> 2, t = lane & 3;
    const int wm = wid & 3, wn = wid >> 2;
    const int bar_id = 1 + wm;

    const float* qbase = q + ((size_t)(b * NH + h) * SS + (size_t)qb * 128) * HD;
    const float* kbase = k + ((size_t)(b * NKV + kvh) * SS) * HD;
    const float* vbase = v + ((size_t)(b * NKV + kvh) * SS) * HD;

    const uint32_t smb = (uint32_t)__cvta_generic_to_shared(sm);

    float* m_s  = (float*)(sm + MS_OFF);
    float* l_s  = (float*)(sm + LS_OFF);
    float* pmax = (float*)(sm + PMAX_OFF);
    float* psum = (float*)(sm + PSUM_OFF);

    // ---- initial async loads: Q (128x128), K tile0, V tile0 ----
#pragma unroll
    for (int i = 0; i < 16; i++) {
        int id = tid + 256 * i;
        int row = id >> 5, c4 = (id & 31) * 4;
        cpa16(smb + (QS_OFF + row * 132 + c4) * 4, qbase + (size_t)row * HD + c4);
    }
#pragma unroll
    for (int i = 0; i < 8; i++) {
        int id = tid + 256 * i;
        int row = id >> 5, c4 = (id & 31) * 4;
        cpa16(smb + (KS_OFF + row * 132 + c4) * 4, kbase + (size_t)row * HD + c4);
        cpa16(smb + (VS_OFF0 + row * 136 + c4) * 4, vbase + (size_t)row * HD + c4);
    }
    asm volatile("cp.async.commit_group;");

    if (tid < 128) { m_s[tid] = -1e30f; l_s[tid] = 0.f; }

    float oacc[2][8][4];
#pragma unroll
    for (int mt = 0; mt < 2; mt++)
#pragma unroll
        for (int nt = 0; nt < 8; nt++)
#pragma unroll
            for (int c = 0; c < 4; c++) oacc[mt][nt][c] = 0.f;

    const int nkv = 2 * qb + 2;

    asm volatile("cp.async.wait_group 0;");
    __syncthreads();

    for (int kvt = 0; kvt < nkv; kvt++) {
        const int cur = kvt & 1;

        // ---- S = Q K^T ----
        float sacc[2][4][4];
#pragma unroll
        for (int mt = 0; mt < 2; mt++)
#pragma unroll
            for (int nt = 0; nt < 4; nt++)
#pragma unroll
                for (int c = 0; c < 4; c++) sacc[mt][nt][c] = 0.f;

        const uint32_t* Qb = sm + QS_OFF + (wm * 32) * 132;
        const uint32_t* Kb = sm + KS_OFF + (wn * 32) * 132;
#pragma unroll
        for (int ks = 0; ks < 16; ks++) {
            const int kb = ks * 8;
            uint32_t a[2][4];
#pragma unroll
            for (int mt = 0; mt < 2; mt++) {
                const uint32_t* Qr = Qb + mt * 16 * 132;
                a[mt][0] = Qr[g * 132 + kb + t];
                a[mt][1] = Qr[(g + 8) * 132 + kb + t];
                a[mt][2] = Qr[g * 132 + kb + t + 4];
                a[mt][3] = Qr[(g + 8) * 132 + kb + t + 4];
            }
#pragma unroll
            for (int nt = 0; nt < 4; nt++) {
                uint32_t b0 = Kb[(nt * 8 + g) * 132 + kb + t];
                uint32_t b1 = Kb[(nt * 8 + g) * 132 + kb + t + 4];
                mma_tf32(sacc[0][nt], a[0], b0, b1);
                mma_tf32(sacc[1][nt], a[1], b0, b1);
            }
        }

        // ---- causal mask (straddling tiles) ----
        if (kvt >= 2 * qb) {
            const int off = (kvt - 2 * qb) * 64;
#pragma unroll
            for (int mt = 0; mt < 2; mt++) {
                int r0 = wm * 32 + mt * 16 + g, r1 = r0 + 8;
#pragma unroll
                for (int nt = 0; nt < 4; nt++) {
                    int c = wn * 32 + nt * 8 + 2 * t + off;
                    if (c     > r0) sacc[mt][nt][0] = -1e30f;
                    if (c + 1 > r0) sacc[mt][nt][1] = -1e30f;
                    if (c     > r1) sacc[mt][nt][2] = -1e30f;
                    if (c + 1 > r1) sacc[mt][nt][3] = -1e30f;
                }
            }
        }

        // ---- row max partials ----
#pragma unroll
        for (int mt = 0; mt < 2; mt++) {
            float rm0 = -1e30f, rm1 = -1e30f;
#pragma unroll
            for (int nt = 0; nt < 4; nt++) {
                rm0 = fmaxf(rm0, fmaxf(sacc[mt][nt][0], sacc[mt][nt][1]));
                rm1 = fmaxf(rm1, fmaxf(sacc[mt][nt][2], sacc[mt][nt][3]));
            }
            rm0 = fmaxf(rm0, __shfl_xor_sync(0xffffffffu, rm0, 1));
            rm0 = fmaxf(rm0, __shfl_xor_sync(0xffffffffu, rm0, 2));
            rm1 = fmaxf(rm1, __shfl_xor_sync(0xffffffffu, rm1, 1));
            rm1 = fmaxf(rm1, __shfl_xor_sync(0xffffffffu, rm1, 2));
            if (t == 0) {
                pmax[wn * 128 + wm * 32 + mt * 16 + g]     = rm0;
                pmax[wn * 128 + wm * 32 + mt * 16 + g + 8] = rm1;
            }
        }
        asm volatile("bar.sync %0, 64;" :: "r"(bar_id) : "memory");

        // ---- softmax: exp, P store (tf32), partial sums ----
        float alpha[2][2], mnew[2][2];
#pragma unroll
        for (int mt = 0; mt < 2; mt++) {
            int r0 = wm * 32 + mt * 16 + g, r1 = r0 + 8;
            float mo0 = m_s[r0], mo1 = m_s[r1];
            float mn0 = fmaxf(mo0, fmaxf(pmax[r0], pmax[128 + r0]));
            float mn1 = fmaxf(mo1, fmaxf(pmax[r1], pmax[128 + r1]));
            alpha[mt][0] = __expf(mo0 - mn0);
            alpha[mt][1] = __expf(mo1 - mn1);
            mnew[mt][0] = mn0; mnew[mt][1] = mn1;
            float rs0 = 0.f, rs1 = 0.f;
#pragma unroll
            for (int nt = 0; nt < 4; nt++) {
                float p00 = __expf(sacc[mt][nt][0] - mn0);
                float p01 = __expf(sacc[mt][nt][1] - mn0);
                float p10 = __expf(sacc[mt][nt][2] - mn1);
                float p11 = __expf(sacc[mt][nt][3] - mn1);
                rs0 += p00 + p01;
                rs1 += p10 + p11;
                int col = wn * 32 + nt * 8 + 2 * t;
                *(uint2*)(sm + PS_OFF + r0 * 68 + col) = make_uint2(f2tf32(p00), f2tf32(p01));
                *(uint2*)(sm + PS_OFF + r1 * 68 + col) = make_uint2(f2tf32(p10), f2tf32(p11));
            }
            rs0 += __shfl_xor_sync(0xffffffffu, rs0, 1);
            rs0 += __shfl_xor_sync(0xffffffffu, rs0, 2);
            rs1 += __shfl_xor_sync(0xffffffffu, rs1, 1);
            rs1 += __shfl_xor_sync(0xffffffffu, rs1, 2);
            if (t == 0) {
                psum[wn * 128 + r0] = rs0;
                psum[wn * 128 + r1] = rs1;
            }
        }
        // rescale O while partner finishes
#pragma unroll
        for (int mt = 0; mt < 2; mt++)
#pragma unroll
            for (int nt = 0; nt < 8; nt++) {
                oacc[mt][nt][0] *= alpha[mt][0];
                oacc[mt][nt][1] *= alpha[mt][0];
                oacc[mt][nt][2] *= alpha[mt][1];
                oacc[mt][nt][3] *= alpha[mt][1];
            }
        asm volatile("bar.sync %0, 64;" :: "r"(bar_id) : "memory");
        if (wn == 0 && t == 0) {
#pragma unroll
            for (int mt = 0; mt < 2; mt++) {
                int r0 = wm * 32 + mt * 16 + g, r1 = r0 + 8;
                l_s[r0] = l_s[r0] * alpha[mt][0] + psum[r0] + psum[128 + r0];
                l_s[r1] = l_s[r1] * alpha[mt][1] + psum[r1] + psum[128 + r1];
                m_s[r0] = mnew[mt][0];
                m_s[r1] = mnew[mt][1];
            }
        }

        // ---- global barrier: all S reads of K done -> prefetch next ----
        __syncthreads();
        if (kvt + 1 < nkv) {
            const float* kn = kbase + (size_t)(kvt + 1) * 64 * HD;
            const float* vn = vbase + (size_t)(kvt + 1) * 64 * HD;
            const uint32_t vo = cur ? VS_OFF0 : VS_OFF1;
#pragma unroll
            for (int i = 0; i < 8; i++) {
                int id = tid + 256 * i;
                int row = id >> 5, c4 = (id & 31) * 4;
                cpa16(smb + (KS_OFF + row * 132 + c4) * 4, kn + (size_t)row * HD + c4);
                cpa16(smb + (vo + row * 136 + c4) * 4, vn + (size_t)row * HD + c4);
            }
            asm volatile("cp.async.commit_group;");
        }

        // ---- O += P V ----
        const uint32_t* Pb = sm + PS_OFF + (wm * 32) * 68;
        const uint32_t* Vb = sm + (cur ? VS_OFF1 : VS_OFF0) + wn * 64;
#pragma unroll
        for (int ks = 0; ks < 8; ks++) {
            const int kb = ks * 8;
            uint32_t a[2][4];
#pragma unroll
            for (int mt = 0; mt < 2; mt++) {
                const uint32_t* Pr = Pb + mt * 16 * 68;
                a[mt][0] = Pr[g * 68 + kb + t];
                a[mt][1] = Pr[(g + 8) * 68 + kb + t];
                a[mt][2] = Pr[g * 68 + kb + t + 4];
                a[mt][3] = Pr[(g + 8) * 68 + kb + t + 4];
            }
#pragma unroll
            for (int nt = 0; nt < 8; nt++) {
                uint32_t b0 = Vb[(kb + t) * 136 + nt * 8 + g];
                uint32_t b1 = Vb[(kb + t + 4) * 136 + nt * 8 + g];
                mma_tf32(oacc[0][nt], a[0], b0, b1);
                mma_tf32(oacc[1][nt], a[1], b0, b1);
            }
        }

        if (kvt + 1 < nkv) {
            asm volatile("cp.async.wait_group 0;");
            __syncthreads();
        }
    }

    // final group sync so l_s updates are visible
    asm volatile("bar.sync %0, 64;" :: "r"(bar_id) : "memory");

    // ---- epilogue ----
#pragma unroll
    for (int mt = 0; mt < 2; mt++) {
        int r0 = wm * 32 + mt * 16 + g, r1 = r0 + 8;
        float linv0 = 1.0f / l_s[r0];
        float linv1 = 1.0f / l_s[r1];
        float* y0 = y + ((size_t)b * SS + (size_t)qb * 128 + r0) * DIM + h * HD + wn * 64;
        float* y1 = y + ((size_t)b * SS + (size_t)qb * 128 + r1) * DIM + h * HD + wn * 64;
#pragma unroll
        for (int nt = 0; nt < 8; nt++) {
            int col = nt * 8 + 2 * t;
            *(float2*)(y0 + col) = make_float2(oacc[mt][nt][0] * linv0,
                                               oacc[mt][nt][1] * linv0);
            *(float2*)(y1 + col) = make_float2(oacc[mt][nt][2] * linv1,
                                               oacc[mt][nt][3] * linv1);
        }
    }
}

// =====================================================================
// host
// =====================================================================
extern "C" void kernel_launch(void* const* d_in, const int* in_sizes, int n_in,
                              void* d_out, int out_size)
{
    const float* x     = (const float*)d_in[0];
    const float* Wq    = (const float*)d_in[1];
    const float* Wk    = (const float*)d_in[2];
    const float* Wv    = (const float*)d_in[3];
    const float* Wproj = (const float*)d_in[4];
    const float* qg    = (const float*)d_in[5];
    float* out = (float*)d_out;

    float *qkv, *q, *k, *v, *y;
    cudaGetSymbolAddress((void**)&qkv, g_qkv);
    cudaGetSymbolAddress((void**)&q,   g_q);
    cudaGetSymbolAddress((void**)&k,   g_k);
    cudaGetSymbolAddress((void**)&v,   g_v);
    cudaGetSymbolAddress((void**)&y,   g_y);

    cudaFuncSetAttribute(attn_mma,
                         cudaFuncAttributeMaxDynamicSharedMemorySize,
                         ATTN_WORDS * sizeof(uint32_t));

    // 0) RoPE tables
    rope_init<<<SS * 32 / 256, 256>>>();

    // 1) QKV projections into g_qkv (ldc = 3072)
    gemm_tf32<<<dim3(DIM / 128, MROWS / 128), 256>>>(x, Wq, qkv, MROWS, DIM, DIM, QKVD, 0);
    gemm_tf32<<<dim3(KVD / 128, MROWS / 128), 256>>>(x, Wk, qkv, MROWS, KVD, DIM, QKVD, DIM);
    gemm_tf32<<<dim3(KVD / 128, MROWS / 128), 256>>>(x, Wv, qkv, MROWS, KVD, DIM, QKVD, DIM + KVD);

    // 2) RMS-norm + RoPE + gain + reshape (tf32 outputs)
    norm_rope<<<dim3(BB * SS, NH + 2 * NKV), 128>>>(qkv, qg, q, k, v);

    // 3) flash attention (Q tile 128) -> g_y
    attn_mma<<<dim3(SS / 128, NH, BB), 256,
               ATTN_WORDS * sizeof(uint32_t)>>>(q, k, v, y);

    // 4) output projection -> d_out
    gemm_tf32<<<dim3(DIM / 128, MROWS / 128), 256>>>(y, Wproj, out, MROWS, DIM, DIM, DIM, 0);
}

// round 6
// speedup vs baseline: 9.5055x; 1.3352x over previous
#include <cuda_runtime.h>
#include <math.h>
#include <stdint.h>

#define DIM 2048
#define NH 16
#define NKV 4
#define HD 128
#define BB 4
#define SS 2048
#define KVD 512        // NKV*HD
#define QKVD 3072      // DIM + 2*KVD
#define MROWS (BB*SS)  // 8192
#define ATTN_SCALE 0.08838834764831845f  // 1/sqrt(128)

// ---------------- scratch (no allocations allowed) ----------------
__device__ float    g_qkv[(size_t)BB*SS*QKVD];     // fp32 gemm outputs
__device__ float    g_q[(size_t)BB*NH*SS*HD];      // tf32 bits (scale folded)
__device__ float    g_k[(size_t)BB*NKV*SS*HD];     // tf32 bits
__device__ float    g_v[(size_t)BB*NKV*SS*HD];     // tf32 bits
__device__ uint32_t g_y[(size_t)BB*SS*DIM];        // tf32 bits (attn out)
__device__ uint32_t g_xt[(size_t)MROWS*DIM];       // tf32 bits of x
__device__ uint32_t g_wt[(size_t)QKVD*DIM];        // tf32 bits of Wq|Wk|Wv
__device__ uint32_t g_wpt[(size_t)DIM*DIM];        // tf32 bits of Wproj
__device__ float    g_cosr[SS*32];
__device__ float    g_sinr[SS*32];

// =====================================================================
// tf32 helpers
// =====================================================================
__device__ __forceinline__ uint32_t f2tf32(float f) {
    uint32_t r;
    asm("cvt.rna.tf32.f32 %0, %1;" : "=r"(r) : "f"(f));
    return r;
}

__device__ __forceinline__ void mma_tf32(float* c, const uint32_t* a,
                                         uint32_t b0, uint32_t b1) {
    asm volatile(
        "mma.sync.aligned.m16n8k8.row.col.f32.tf32.tf32.f32 "
        "{%0,%1,%2,%3}, {%4,%5,%6,%7}, {%8,%9}, {%0,%1,%2,%3};"
        : "+f"(c[0]), "+f"(c[1]), "+f"(c[2]), "+f"(c[3])
        : "r"(a[0]), "r"(a[1]), "r"(a[2]), "r"(a[3]), "r"(b0), "r"(b1));
}

__device__ __forceinline__ void cpa16(uint32_t dst, const void* src) {
    asm volatile("cp.async.cg.shared.global [%0], [%1], 16;"
                 :: "r"(dst), "l"(src));
}

// =====================================================================
// elementwise fp32 -> tf32-bit conversion (vectorized)
// =====================================================================
__global__ void to_tf32(const float4* __restrict__ src,
                        uint4* __restrict__ dst, int n4)
{
    int i = blockIdx.x * blockDim.x + threadIdx.x;
    if (i < n4) {
        float4 v = src[i];
        dst[i] = make_uint4(f2tf32(v.x), f2tf32(v.y), f2tf32(v.z), f2tf32(v.w));
    }
}

// =====================================================================
// tf32 GEMM on pre-converted operands. C[m, coloff+n] = sum_k A[m,k]*W[n,k].
// 128x128x32 tiles, cp.async double-buffered, both tiles stored [row][k]
// stride 36 (==4 mod 32 -> conflict-free 4g+t fragment reads), no smem
// stores through the register path, no cvt in the hot loop.
// dynamic smem: 2*(128*36)*2 words = 73,728 B.
// =====================================================================
#define GA(bf) ((bf) * 4608)
#define GB(bf) (9216 + (bf) * 4608)
#define GEMM_SMEM_BYTES 73728

__global__ __launch_bounds__(256, 2)
void gemm_pre(const uint32_t* __restrict__ A, const uint32_t* __restrict__ W,
              float* __restrict__ C, int M, int N, int K, int ldc, int coloff)
{
    extern __shared__ uint32_t sm[];
    const int tid  = threadIdx.x;
    const int lane = tid & 31;
    const int wid  = tid >> 5;
    const int wm   = wid & 3;
    const int wn   = wid >> 2;
    const int g    = lane >> 2;
    const int t    = lane & 3;
    const int m0   = blockIdx.y * 128;
    const int n0   = blockIdx.x * 128;
    const uint32_t smb = (uint32_t)__cvta_generic_to_shared(sm);

    float acc[2][8][4];
#pragma unroll
    for (int mt = 0; mt < 2; mt++)
#pragma unroll
        for (int nt = 0; nt < 8; nt++)
#pragma unroll
            for (int c = 0; c < 4; c++) acc[mt][nt][c] = 0.f;

    const int ntiles = K >> 5;

    // prologue: tile 0 -> buffer 0
#pragma unroll
    for (int r = 0; r < 4; r++) {
        int id = tid + 256 * r;
        int row = id >> 3, c4 = (id & 7) * 4;
        cpa16(smb + (GA(0) + row * 36 + c4) * 4, A + (size_t)(m0 + row) * K + c4);
        cpa16(smb + (GB(0) + row * 36 + c4) * 4, W + (size_t)(n0 + row) * K + c4);
    }
    asm volatile("cp.async.commit_group;");

    for (int it = 0; it < ntiles; it++) {
        const int bf = it & 1;
        if (it + 1 < ntiles) {
            const int k0 = (it + 1) * 32;
#pragma unroll
            for (int r = 0; r < 4; r++) {
                int id = tid + 256 * r;
                int row = id >> 3, c4 = (id & 7) * 4;
                cpa16(smb + (GA(bf ^ 1) + row * 36 + c4) * 4,
                      A + (size_t)(m0 + row) * K + k0 + c4);
                cpa16(smb + (GB(bf ^ 1) + row * 36 + c4) * 4,
                      W + (size_t)(n0 + row) * K + k0 + c4);
            }
            asm volatile("cp.async.commit_group;");
            asm volatile("cp.async.wait_group 1;");
        } else {
            asm volatile("cp.async.wait_group 0;");
        }
        __syncthreads();

        const uint32_t* As = sm + GA(bf);
        const uint32_t* Bs = sm + GB(bf);
#pragma unroll
        for (int kc = 0; kc < 4; kc++) {
            const int kb = kc * 8;
            uint32_t a[2][4];
#pragma unroll
            for (int mt = 0; mt < 2; mt++) {
                int rb = wm * 32 + mt * 16;
                a[mt][0] = As[(rb + g    ) * 36 + kb + t    ];
                a[mt][1] = As[(rb + g + 8) * 36 + kb + t    ];
                a[mt][2] = As[(rb + g    ) * 36 + kb + t + 4];
                a[mt][3] = As[(rb + g + 8) * 36 + kb + t + 4];
            }
#pragma unroll
            for (int nt = 0; nt < 8; nt++) {
                int nb = wn * 64 + nt * 8 + g;
                uint32_t b0 = Bs[nb * 36 + kb + t    ];
                uint32_t b1 = Bs[nb * 36 + kb + t + 4];
                mma_tf32(acc[0][nt], a[0], b0, b1);
                mma_tf32(acc[1][nt], a[1], b0, b1);
            }
        }
        __syncthreads();
    }

#pragma unroll
    for (int mt = 0; mt < 2; mt++) {
        int row = m0 + wm * 32 + mt * 16 + g;
#pragma unroll
        for (int nt = 0; nt < 8; nt++) {
            int col = coloff + n0 + wn * 64 + nt * 8 + 2 * t;
            float2 v01 = make_float2(acc[mt][nt][0], acc[mt][nt][1]);
            float2 v23 = make_float2(acc[mt][nt][2], acc[mt][nt][3]);
            *(float2*)(C + (size_t)row * ldc + col)       = v01;
            *(float2*)(C + (size_t)(row + 8) * ldc + col) = v23;
        }
    }
}

// =====================================================================
// RoPE table init
// =====================================================================
__global__ void rope_init()
{
    int i = blockIdx.x * blockDim.x + threadIdx.x;
    int s = i >> 5, f = i & 31;
    double inv = pow(10000.0, -(double)f / 32.0);
    double ang = (double)s * inv;
    double sd, cd;
    sincos(ang, &sd, &cd);
    g_cosr[i] = (float)cd;
    g_sinr[i] = (float)sd;
}

// =====================================================================
// RMS-norm + RoPE + gain + reshape; q/k/v stored as tf32 bits
// =====================================================================
__global__ void norm_rope(const float* __restrict__ qkv,
                          const float* __restrict__ q_gain,
                          float* __restrict__ q, float* __restrict__ k,
                          float* __restrict__ v)
{
    const int bs   = blockIdx.x;
    const int head = blockIdx.y;
    const int b = bs / SS, s = bs % SS;
    const int d = threadIdx.x;

    if (head >= NH + NKV) {            // V: convert + reshape
        int kv = head - NH - NKV;
        float val = qkv[(size_t)bs * QKVD + DIM + KVD + kv * HD + d];
        v[((size_t)(b * NKV + kv) * SS + s) * HD + d] = __uint_as_float(f2tf32(val));
        return;
    }
    const bool isq = (head < NH);
    const float* row = qkv + (size_t)bs * QKVD +
                       (isq ? head * HD : DIM + (head - NH) * HD);
    float val = row[d];

    __shared__ float red[4];
    __shared__ float xs[HD];
    float sq = val * val;
#pragma unroll
    for (int o = 16; o > 0; o >>= 1) sq += __shfl_xor_sync(0xffffffffu, sq, o);
    if ((d & 31) == 0) red[d >> 5] = sq;
    __syncthreads();
    float ms = (red[0] + red[1] + red[2] + red[3]) * (1.0f / HD);
    float xn = val * rsqrtf(ms + 1.1920929e-07f);
    xs[d] = xn;
    __syncthreads();

    float outv;
    if (d < 64) {
        int f = d & 31;
        float c  = g_cosr[s * 32 + f];
        float sn = g_sinr[s * 32 + f];
        float x1 = xs[f], x2 = xs[f + 32];
        outv = (d < 32) ? (x1 * c + x2 * sn) : (-x1 * sn + x2 * c);
    } else {
        outv = xn;
    }

    if (isq) {
        outv *= q_gain[head] * ATTN_SCALE;
        q[((size_t)(b * NH + head) * SS + s) * HD + d] = __uint_as_float(f2tf32(outv));
    } else {
        int kv = head - NH;
        k[((size_t)(b * NKV + kv) * SS + s) * HD + d] = __uint_as_float(f2tf32(outv));
    }
}

// =====================================================================
// tf32 flash attention (unchanged from R4 except epilogue emits tf32 bits)
// =====================================================================
#define QS_OFF   0            // 128 x 132
#define KS_OFF   16896        // 64 x 132
#define VS_OFF0  25344        // 64 x 136
#define VS_OFF1  34048
#define PS_OFF   42752        // 128 x 68
#define PMAX_OFF 51456        // [2][128]
#define PSUM_OFF 51712        // [2][128]
#define MS_OFF   51968        // [128]
#define LS_OFF   52096        // [128]
#define ATTN_WORDS 52224      // 208,896 bytes

__global__ __launch_bounds__(256, 1)
void attn_mma(const float* __restrict__ q, const float* __restrict__ k,
              const float* __restrict__ v, uint32_t* __restrict__ y)
{
    extern __shared__ uint32_t sm[];
    const int qb = (int)gridDim.x - 1 - (int)blockIdx.x;   // heavy CTAs first
    const int h = blockIdx.y, b = blockIdx.z;
    const int kvh = h >> 2;
    const int tid = threadIdx.x;
    const int lane = tid & 31, wid = tid >> 5;
    const int g = lane >> 2, t = lane & 3;
    const int wm = wid & 3, wn = wid >> 2;
    const int bar_id = 1 + wm;

    const float* qbase = q + ((size_t)(b * NH + h) * SS + (size_t)qb * 128) * HD;
    const float* kbase = k + ((size_t)(b * NKV + kvh) * SS) * HD;
    const float* vbase = v + ((size_t)(b * NKV + kvh) * SS) * HD;

    const uint32_t smb = (uint32_t)__cvta_generic_to_shared(sm);

    float* m_s  = (float*)(sm + MS_OFF);
    float* l_s  = (float*)(sm + LS_OFF);
    float* pmax = (float*)(sm + PMAX_OFF);
    float* psum = (float*)(sm + PSUM_OFF);

#pragma unroll
    for (int i = 0; i < 16; i++) {
        int id = tid + 256 * i;
        int row = id >> 5, c4 = (id & 31) * 4;
        cpa16(smb + (QS_OFF + row * 132 + c4) * 4, qbase + (size_t)row * HD + c4);
    }
#pragma unroll
    for (int i = 0; i < 8; i++) {
        int id = tid + 256 * i;
        int row = id >> 5, c4 = (id & 31) * 4;
        cpa16(smb + (KS_OFF + row * 132 + c4) * 4, kbase + (size_t)row * HD + c4);
        cpa16(smb + (VS_OFF0 + row * 136 + c4) * 4, vbase + (size_t)row * HD + c4);
    }
    asm volatile("cp.async.commit_group;");

    if (tid < 128) { m_s[tid] = -1e30f; l_s[tid] = 0.f; }

    float oacc[2][8][4];
#pragma unroll
    for (int mt = 0; mt < 2; mt++)
#pragma unroll
        for (int nt = 0; nt < 8; nt++)
#pragma unroll
            for (int c = 0; c < 4; c++) oacc[mt][nt][c] = 0.f;

    const int nkv = 2 * qb + 2;

    asm volatile("cp.async.wait_group 0;");
    __syncthreads();

    for (int kvt = 0; kvt < nkv; kvt++) {
        const int cur = kvt & 1;

        float sacc[2][4][4];
#pragma unroll
        for (int mt = 0; mt < 2; mt++)
#pragma unroll
            for (int nt = 0; nt < 4; nt++)
#pragma unroll
                for (int c = 0; c < 4; c++) sacc[mt][nt][c] = 0.f;

        const uint32_t* Qb = sm + QS_OFF + (wm * 32) * 132;
        const uint32_t* Kb = sm + KS_OFF + (wn * 32) * 132;
#pragma unroll
        for (int ks = 0; ks < 16; ks++) {
            const int kb = ks * 8;
            uint32_t a[2][4];
#pragma unroll
            for (int mt = 0; mt < 2; mt++) {
                const uint32_t* Qr = Qb + mt * 16 * 132;
                a[mt][0] = Qr[g * 132 + kb + t];
                a[mt][1] = Qr[(g + 8) * 132 + kb + t];
                a[mt][2] = Qr[g * 132 + kb + t + 4];
                a[mt][3] = Qr[(g + 8) * 132 + kb + t + 4];
            }
#pragma unroll
            for (int nt = 0; nt < 4; nt++) {
                uint32_t b0 = Kb[(nt * 8 + g) * 132 + kb + t];
                uint32_t b1 = Kb[(nt * 8 + g) * 132 + kb + t + 4];
                mma_tf32(sacc[0][nt], a[0], b0, b1);
                mma_tf32(sacc[1][nt], a[1], b0, b1);
            }
        }

        if (kvt >= 2 * qb) {
            const int off = (kvt - 2 * qb) * 64;
#pragma unroll
            for (int mt = 0; mt < 2; mt++) {
                int r0 = wm * 32 + mt * 16 + g, r1 = r0 + 8;
#pragma unroll
                for (int nt = 0; nt < 4; nt++) {
                    int c = wn * 32 + nt * 8 + 2 * t + off;
                    if (c     > r0) sacc[mt][nt][0] = -1e30f;
                    if (c + 1 > r0) sacc[mt][nt][1] = -1e30f;
                    if (c     > r1) sacc[mt][nt][2] = -1e30f;
                    if (c + 1 > r1) sacc[mt][nt][3] = -1e30f;
                }
            }
        }

#pragma unroll
        for (int mt = 0; mt < 2; mt++) {
            float rm0 = -1e30f, rm1 = -1e30f;
#pragma unroll
            for (int nt = 0; nt < 4; nt++) {
                rm0 = fmaxf(rm0, fmaxf(sacc[mt][nt][0], sacc[mt][nt][1]));
                rm1 = fmaxf(rm1, fmaxf(sacc[mt][nt][2], sacc[mt][nt][3]));
            }
            rm0 = fmaxf(rm0, __shfl_xor_sync(0xffffffffu, rm0, 1));
            rm0 = fmaxf(rm0, __shfl_xor_sync(0xffffffffu, rm0, 2));
            rm1 = fmaxf(rm1, __shfl_xor_sync(0xffffffffu, rm1, 1));
            rm1 = fmaxf(rm1, __shfl_xor_sync(0xffffffffu, rm1, 2));
            if (t == 0) {
                pmax[wn * 128 + wm * 32 + mt * 16 + g]     = rm0;
                pmax[wn * 128 + wm * 32 + mt * 16 + g + 8] = rm1;
            }
        }
        asm volatile("bar.sync %0, 64;" :: "r"(bar_id) : "memory");

        float alpha[2][2], mnew[2][2];
#pragma unroll
        for (int mt = 0; mt < 2; mt++) {
            int r0 = wm * 32 + mt * 16 + g, r1 = r0 + 8;
            float mo0 = m_s[r0], mo1 = m_s[r1];
            float mn0 = fmaxf(mo0, fmaxf(pmax[r0], pmax[128 + r0]));
            float mn1 = fmaxf(mo1, fmaxf(pmax[r1], pmax[128 + r1]));
            alpha[mt][0] = __expf(mo0 - mn0);
            alpha[mt][1] = __expf(mo1 - mn1);
            mnew[mt][0] = mn0; mnew[mt][1] = mn1;
            float rs0 = 0.f, rs1 = 0.f;
#pragma unroll
            for (int nt = 0; nt < 4; nt++) {
                float p00 = __expf(sacc[mt][nt][0] - mn0);
                float p01 = __expf(sacc[mt][nt][1] - mn0);
                float p10 = __expf(sacc[mt][nt][2] - mn1);
                float p11 = __expf(sacc[mt][nt][3] - mn1);
                rs0 += p00 + p01;
                rs1 += p10 + p11;
                int col = wn * 32 + nt * 8 + 2 * t;
                *(uint2*)(sm + PS_OFF + r0 * 68 + col) = make_uint2(f2tf32(p00), f2tf32(p01));
                *(uint2*)(sm + PS_OFF + r1 * 68 + col) = make_uint2(f2tf32(p10), f2tf32(p11));
            }
            rs0 += __shfl_xor_sync(0xffffffffu, rs0, 1);
            rs0 += __shfl_xor_sync(0xffffffffu, rs0, 2);
            rs1 += __shfl_xor_sync(0xffffffffu, rs1, 1);
            rs1 += __shfl_xor_sync(0xffffffffu, rs1, 2);
            if (t == 0) {
                psum[wn * 128 + r0] = rs0;
                psum[wn * 128 + r1] = rs1;
            }
        }
#pragma unroll
        for (int mt = 0; mt < 2; mt++)
#pragma unroll
            for (int nt = 0; nt < 8; nt++) {
                oacc[mt][nt][0] *= alpha[mt][0];
                oacc[mt][nt][1] *= alpha[mt][0];
                oacc[mt][nt][2] *= alpha[mt][1];
                oacc[mt][nt][3] *= alpha[mt][1];
            }
        asm volatile("bar.sync %0, 64;" :: "r"(bar_id) : "memory");
        if (wn == 0 && t == 0) {
#pragma unroll
            for (int mt = 0; mt < 2; mt++) {
                int r0 = wm * 32 + mt * 16 + g, r1 = r0 + 8;
                l_s[r0] = l_s[r0] * alpha[mt][0] + psum[r0] + psum[128 + r0];
                l_s[r1] = l_s[r1] * alpha[mt][1] + psum[r1] + psum[128 + r1];
                m_s[r0] = mnew[mt][0];
                m_s[r1] = mnew[mt][1];
            }
        }

        __syncthreads();
        if (kvt + 1 < nkv) {
            const float* kn = kbase + (size_t)(kvt + 1) * 64 * HD;
            const float* vn = vbase + (size_t)(kvt + 1) * 64 * HD;
            const uint32_t vo = cur ? VS_OFF0 : VS_OFF1;
#pragma unroll
            for (int i = 0; i < 8; i++) {
                int id = tid + 256 * i;
                int row = id >> 5, c4 = (id & 31) * 4;
                cpa16(smb + (KS_OFF + row * 132 + c4) * 4, kn + (size_t)row * HD + c4);
                cpa16(smb + (vo + row * 136 + c4) * 4, vn + (size_t)row * HD + c4);
            }
            asm volatile("cp.async.commit_group;");
        }

        const uint32_t* Pb = sm + PS_OFF + (wm * 32) * 68;
        const uint32_t* Vb = sm + (cur ? VS_OFF1 : VS_OFF0) + wn * 64;
#pragma unroll
        for (int ks = 0; ks < 8; ks++) {
            const int kb = ks * 8;
            uint32_t a[2][4];
#pragma unroll
            for (int mt = 0; mt < 2; mt++) {
                const uint32_t* Pr = Pb + mt * 16 * 68;
                a[mt][0] = Pr[g * 68 + kb + t];
                a[mt][1] = Pr[(g + 8) * 68 + kb + t];
                a[mt][2] = Pr[g * 68 + kb + t + 4];
                a[mt][3] = Pr[(g + 8) * 68 + kb + t + 4];
            }
#pragma unroll
            for (int nt = 0; nt < 8; nt++) {
                uint32_t b0 = Vb[(kb + t) * 136 + nt * 8 + g];
                uint32_t b1 = Vb[(kb + t + 4) * 136 + nt * 8 + g];
                mma_tf32(oacc[0][nt], a[0], b0, b1);
                mma_tf32(oacc[1][nt], a[1], b0, b1);
            }
        }

        if (kvt + 1 < nkv) {
            asm volatile("cp.async.wait_group 0;");
            __syncthreads();
        }
    }

    asm volatile("bar.sync %0, 64;" :: "r"(bar_id) : "memory");

    // ---- epilogue: normalize, emit tf32 bits for the proj gemm ----
#pragma unroll
    for (int mt = 0; mt < 2; mt++) {
        int r0 = wm * 32 + mt * 16 + g, r1 = r0 + 8;
        float linv0 = 1.0f / l_s[r0];
        float linv1 = 1.0f / l_s[r1];
        uint32_t* y0 = y + ((size_t)b * SS + (size_t)qb * 128 + r0) * DIM + h * HD + wn * 64;
        uint32_t* y1 = y + ((size_t)b * SS + (size_t)qb * 128 + r1) * DIM + h * HD + wn * 64;
#pragma unroll
        for (int nt = 0; nt < 8; nt++) {
            int col = nt * 8 + 2 * t;
            *(uint2*)(y0 + col) = make_uint2(f2tf32(oacc[mt][nt][0] * linv0),
                                             f2tf32(oacc[mt][nt][1] * linv0));
            *(uint2*)(y1 + col) = make_uint2(f2tf32(oacc[mt][nt][2] * linv1),
                                             f2tf32(oacc[mt][nt][3] * linv1));
        }
    }
}

// =====================================================================
// host
// =====================================================================
extern "C" void kernel_launch(void* const* d_in, const int* in_sizes, int n_in,
                              void* d_out, int out_size)
{
    const float* x     = (const float*)d_in[0];
    const float* Wq    = (const float*)d_in[1];
    const float* Wk    = (const float*)d_in[2];
    const float* Wv    = (const float*)d_in[3];
    const float* Wproj = (const float*)d_in[4];
    const float* qg    = (const float*)d_in[5];
    float* out = (float*)d_out;

    float *qkv, *q, *k, *v;
    uint32_t *y, *xt, *wt, *wpt;
    cudaGetSymbolAddress((void**)&qkv, g_qkv);
    cudaGetSymbolAddress((void**)&q,   g_q);
    cudaGetSymbolAddress((void**)&k,   g_k);
    cudaGetSymbolAddress((void**)&v,   g_v);
    cudaGetSymbolAddress((void**)&y,   g_y);
    cudaGetSymbolAddress((void**)&xt,  g_xt);
    cudaGetSymbolAddress((void**)&wt,  g_wt);
    cudaGetSymbolAddress((void**)&wpt, g_wpt);

    cudaFuncSetAttribute(attn_mma,
                         cudaFuncAttributeMaxDynamicSharedMemorySize,
                         ATTN_WORDS * sizeof(uint32_t));
    cudaFuncSetAttribute(gemm_pre,
                         cudaFuncAttributeMaxDynamicSharedMemorySize,
                         GEMM_SMEM_BYTES);

    // 0) RoPE tables + tf32 pre-conversions
    rope_init<<<SS * 32 / 256, 256>>>();
    to_tf32<<<(MROWS * DIM / 4 + 255) / 256, 256>>>((const float4*)x, (uint4*)xt, MROWS * DIM / 4);
    to_tf32<<<(DIM * DIM / 4 + 255) / 256, 256>>>((const float4*)Wq, (uint4*)wt, DIM * DIM / 4);
    to_tf32<<<(KVD * DIM / 4 + 255) / 256, 256>>>((const float4*)Wk, (uint4*)(wt + (size_t)DIM * DIM), KVD * DIM / 4);
    to_tf32<<<(KVD * DIM / 4 + 255) / 256, 256>>>((const float4*)Wv, (uint4*)(wt + (size_t)(DIM + KVD) * DIM), KVD * DIM / 4);
    to_tf32<<<(DIM * DIM / 4 + 255) / 256, 256>>>((const float4*)Wproj, (uint4*)wpt, DIM * DIM / 4);

    // 1) QKV projections into g_qkv (ldc = 3072)
    gemm_pre<<<dim3(DIM / 128, MROWS / 128), 256, GEMM_SMEM_BYTES>>>(
        xt, wt, qkv, MROWS, DIM, DIM, QKVD, 0);
    gemm_pre<<<dim3(KVD / 128, MROWS / 128), 256, GEMM_SMEM_BYTES>>>(
        xt, wt + (size_t)DIM * DIM, qkv, MROWS, KVD, DIM, QKVD, DIM);
    gemm_pre<<<dim3(KVD / 128, MROWS / 128), 256, GEMM_SMEM_BYTES>>>(
        xt, wt + (size_t)(DIM + KVD) * DIM, qkv, MROWS, KVD, DIM, QKVD, DIM + KVD);

    // 2) RMS-norm + RoPE + gain + reshape (tf32 outputs)
    norm_rope<<<dim3(BB * SS, NH + 2 * NKV), 128>>>(qkv, qg, q, k, v);

    // 3) flash attention (Q tile 128) -> g_y (tf32 bits)
    attn_mma<<<dim3(SS / 128, NH, BB), 256,
               ATTN_WORDS * sizeof(uint32_t)>>>(q, k, v, y);

    // 4) output projection -> d_out
    gemm_pre<<<dim3(DIM / 128, MROWS / 128), 256, GEMM_SMEM_BYTES>>>(
        y, wpt, out, MROWS, DIM, DIM, DIM, 0);
}